// round 2
// baseline (speedup 1.0000x reference)
#include <cuda_runtime.h>
#include <cuda_bf16.h>
#include <math.h>

// Problem constants
#define B_   4
#define N_   4096
#define C_   512
#define NH_  8
#define HD_  64
#define NK_  1024   // (64/2)*(64/2)
#define KCONV 2048  // C*SR*SR

// ---------------- scratch (device globals; no runtime allocation) ----------------
__device__ float g_q  [B_ * N_  * C_];        // q projection   [B,N,C]  (c = h*64+d)
__device__ float g_xr [B_ * NK_ * C_];        // reduced x      [B,Nk,C]
__device__ float g_kv [B_ * NK_ * 2 * C_];    // kv projection  [B,Nk,2C]
__device__ float g_ao [B_ * N_  * C_];        // attention out  [B,N,C]
__device__ float g_wqT [C_ * C_];             // q_w^T     [K=512][N=512]
__device__ float g_wkvT[C_ * 2 * C_];         // kv_w^T    [K=512][N=1024]
__device__ float g_wsr [KCONV * C_];          // sr_w reord[K=2048][N=512], k=ij*512+ci
__device__ float g_wprT[C_ * C_];             // proj_w^T  [K=512][N=512]

// ---------------- weight transpose: w[Nr][Kc] -> wt[Kc][Nr] ----------------
__global__ void transpose_k(const float* __restrict__ w, float* __restrict__ wt,
                            int Nr, int Kc) {
    __shared__ float t[32][33];
    int k0 = blockIdx.x * 32, n0 = blockIdx.y * 32;
    int x = threadIdx.x, y = threadIdx.y;   // 32 x 8
#pragma unroll
    for (int yy = y; yy < 32; yy += 8)
        t[yy][x] = w[(size_t)(n0 + yy) * Kc + k0 + x];
    __syncthreads();
#pragma unroll
    for (int yy = y; yy < 32; yy += 8)
        wt[(size_t)(k0 + yy) * Nr + n0 + x] = t[x][yy];
}

// sr_w[n][ci][i][j]  ->  wsr[(ij*512+ci)*512 + n]
__global__ void reorder_sr(const float* __restrict__ w, float* __restrict__ wt) {
    int idx = blockIdx.x * 256 + threadIdx.x;     // over 2048*512
    if (idx >= KCONV * C_) return;
    int k = idx >> 9;          // /512 -> k index
    int n = idx & 511;
    int ij = k >> 9;           // k = ij*512 + ci
    int ci = k & 511;
    wt[idx] = w[(size_t)n * KCONV + ci * 4 + ij];
}

// ---------------- fp32 SGEMM: C[M,N] = A @ B' (+bias), B' is [K][N] ----------------
// 128x128 tile, KT=16, 256 threads, 8x8 per thread.
// MODE 0: A[m][k] row-major.  MODE 1: conv gather (m->(b,p), k=ij*512+ci).
template <int MODE>
__global__ __launch_bounds__(256)
void gemm128(const float* __restrict__ A, const float* __restrict__ Bm,
             const float* __restrict__ bias, float* __restrict__ Cc,
             int M, int N, int K) {
    __shared__ float As[16][132];   // transposed: As[kk][m], pad kills store conflicts
    __shared__ float Bs[16][128];   // Bs[kk][n]

    const int tid = threadIdx.x;
    const int tx = tid & 15, ty = tid >> 4;
    const int bx = blockIdx.x * 128, by = blockIdx.y * 128;

    float acc[8][8];
#pragma unroll
    for (int i = 0; i < 8; i++)
#pragma unroll
        for (int j = 0; j < 8; j++) acc[i][j] = 0.f;

    const int a_row  = tid >> 2;          // 0..63 (two passes of 64 rows)
    const int a_col4 = (tid & 3) << 2;    // 0,4,8,12
    const int b_k    = tid >> 5;          // 0..7 (two passes)
    const int b_n4   = (tid & 31) << 2;   // 0..124

    for (int k0 = 0; k0 < K; k0 += 16) {
#pragma unroll
        for (int p = 0; p < 2; p++) {
            int m = by + a_row + p * 64;
            int k = k0 + a_col4;
            size_t off;
            if (MODE == 0) {
                off = (size_t)m * K + k;
            } else {
                int bb = m >> 10;  int pp = m & 1023;
                int ph = pp >> 5;  int pw = pp & 31;
                int ij = k >> 9;   int ci = k & 511;
                int i = ij >> 1,   j = ij & 1;
                int pix = (2 * ph + i) * 64 + (2 * pw + j);
                off = ((size_t)bb * N_ + pix) * C_ + ci;
            }
            float4 v = *reinterpret_cast<const float4*>(A + off);
            As[a_col4 + 0][a_row + p * 64] = v.x;
            As[a_col4 + 1][a_row + p * 64] = v.y;
            As[a_col4 + 2][a_row + p * 64] = v.z;
            As[a_col4 + 3][a_row + p * 64] = v.w;
        }
#pragma unroll
        for (int p = 0; p < 2; p++) {
            int k = b_k + p * 8;
            float4 v = *reinterpret_cast<const float4*>(Bm + (size_t)(k0 + k) * N + bx + b_n4);
            *reinterpret_cast<float4*>(&Bs[k][b_n4]) = v;
        }
        __syncthreads();

#pragma unroll
        for (int kk = 0; kk < 16; kk++) {
            float a[8], b[8];
            *(float4*)&a[0] = *(float4*)&As[kk][ty * 8];
            *(float4*)&a[4] = *(float4*)&As[kk][ty * 8 + 4];
            *(float4*)&b[0] = *(float4*)&Bs[kk][tx * 8];
            *(float4*)&b[4] = *(float4*)&Bs[kk][tx * 8 + 4];
#pragma unroll
            for (int i = 0; i < 8; i++)
#pragma unroll
                for (int j = 0; j < 8; j++)
                    acc[i][j] += a[i] * b[j];
        }
        __syncthreads();
    }

#pragma unroll
    for (int i = 0; i < 8; i++) {
        int m = by + ty * 8 + i;
#pragma unroll
        for (int j = 0; j < 8; j += 4) {
            int n = bx + tx * 8 + j;
            float4 v;
            v.x = acc[i][j];     v.y = acc[i][j + 1];
            v.z = acc[i][j + 2]; v.w = acc[i][j + 3];
            if (bias) {
                v.x += bias[n];     v.y += bias[n + 1];
                v.z += bias[n + 2]; v.w += bias[n + 3];
            }
            *reinterpret_cast<float4*>(Cc + (size_t)m * N + n) = v;
        }
    }
}

// ---------------- fused attention (flash-style, fp32) ----------------
// grid: (N/64, nh, B); 256 threads. Per block: 64 queries of one (b,h).
// Thread (tx,ty) owns rows i=4ty+ii; S cols j=tx+16q; out cols d=4tx+jj.
#define ATTN_SMEM ((64*64 + 64*68 + 64*64 + 64*64) * 4)

__global__ __launch_bounds__(256)
void attn_kernel(const float* __restrict__ Q, const float* __restrict__ KV,
                 float* __restrict__ O) {
    extern __shared__ float sm[];
    float* Qs = sm;                // [64][64]
    float* Ks = Qs + 64 * 64;      // [64][68]  (pad 68 -> conflict-free strided reads)
    float* Vs = Ks + 64 * 68;      // [64][64]
    float* Ps = Vs + 64 * 64;      // [64][64]

    const int tid = threadIdx.x;
    const int tx = tid & 15, ty = tid >> 4;
    const int qb = blockIdx.x * 64;
    const int h  = blockIdx.y;
    const int b  = blockIdx.z;
    const float scale = 0.125f;    // hd^-0.5

    // load Q tile [64 rows][64 dims]
    const float* qg = Q + ((size_t)(b * N_ + qb)) * C_ + h * HD_;
#pragma unroll
    for (int r = 0; r < 4; r++) {
        int idx = tid + r * 256;                  // float4 slot
        int row = idx >> 4, c4 = (idx & 15) << 2;
        float4 v = *reinterpret_cast<const float4*>(qg + (size_t)row * C_ + c4);
        *reinterpret_cast<float4*>(Qs + row * 64 + c4) = v;
    }

    float m_[4], l_[4], acc[4][4];
#pragma unroll
    for (int i = 0; i < 4; i++) {
        m_[i] = -1e30f; l_[i] = 0.f;
#pragma unroll
        for (int j = 0; j < 4; j++) acc[i][j] = 0.f;
    }

    const float* kvg = KV + (size_t)b * NK_ * (2 * C_);

    for (int t = 0; t < NK_ / 64; t++) {
        __syncthreads();
        int p0 = t * 64;
#pragma unroll
        for (int r = 0; r < 4; r++) {
            int idx = tid + r * 256;
            int row = idx >> 4, c4 = (idx & 15) << 2;
            const float* base = kvg + (size_t)(p0 + row) * (2 * C_) + h * HD_ + c4;
            float4 kvec = *reinterpret_cast<const float4*>(base);
            float4 vvec = *reinterpret_cast<const float4*>(base + C_);
            *reinterpret_cast<float4*>(Ks + row * 68 + c4) = kvec;
            *reinterpret_cast<float4*>(Vs + row * 64 + c4) = vvec;
        }
        __syncthreads();

        // S = Q K^T   (rows 4ty+i, cols tx+16q)
        float s[4][4];
#pragma unroll
        for (int i = 0; i < 4; i++)
#pragma unroll
            for (int q = 0; q < 4; q++) s[i][q] = 0.f;

#pragma unroll
        for (int d = 0; d < 64; d += 4) {
            float4 qv[4], kv4[4];
#pragma unroll
            for (int i = 0; i < 4; i++)
                qv[i] = *reinterpret_cast<float4*>(Qs + (4 * ty + i) * 64 + d);
#pragma unroll
            for (int q = 0; q < 4; q++)
                kv4[q] = *reinterpret_cast<float4*>(Ks + (tx + 16 * q) * 68 + d);
#pragma unroll
            for (int i = 0; i < 4; i++)
#pragma unroll
                for (int q = 0; q < 4; q++)
                    s[i][q] += qv[i].x * kv4[q].x + qv[i].y * kv4[q].y +
                               qv[i].z * kv4[q].z + qv[i].w * kv4[q].w;
        }

        // online softmax update per row
#pragma unroll
        for (int i = 0; i < 4; i++) {
#pragma unroll
            for (int q = 0; q < 4; q++) s[i][q] *= scale;
            float mx = fmaxf(fmaxf(s[i][0], s[i][1]), fmaxf(s[i][2], s[i][3]));
#pragma unroll
            for (int o = 8; o >= 1; o >>= 1)
                mx = fmaxf(mx, __shfl_xor_sync(0xffffffffu, mx, o));
            float mn = fmaxf(m_[i], mx);
            float al = __expf(m_[i] - mn);
            float p[4], sum = 0.f;
#pragma unroll
            for (int q = 0; q < 4; q++) { p[q] = __expf(s[i][q] - mn); sum += p[q]; }
#pragma unroll
            for (int o = 8; o >= 1; o >>= 1)
                sum += __shfl_xor_sync(0xffffffffu, sum, o);
            l_[i] = l_[i] * al + sum;
            m_[i] = mn;
#pragma unroll
            for (int j = 0; j < 4; j++) acc[i][j] *= al;
#pragma unroll
            for (int q = 0; q < 4; q++)
                Ps[(4 * ty + i) * 64 + tx + 16 * q] = p[q];
        }
        __syncthreads();

        // acc += P @ V   (out cols 4tx+jj)
#pragma unroll
        for (int j0 = 0; j0 < 64; j0 += 4) {
            float4 pv[4], vv[4];
#pragma unroll
            for (int i = 0; i < 4; i++)
                pv[i] = *reinterpret_cast<float4*>(Ps + (4 * ty + i) * 64 + j0);
#pragma unroll
            for (int q = 0; q < 4; q++)
                vv[q] = *reinterpret_cast<float4*>(Vs + (j0 + q) * 64 + 4 * tx);
#pragma unroll
            for (int i = 0; i < 4; i++) {
                acc[i][0] += pv[i].x * vv[0].x + pv[i].y * vv[1].x + pv[i].z * vv[2].x + pv[i].w * vv[3].x;
                acc[i][1] += pv[i].x * vv[0].y + pv[i].y * vv[1].y + pv[i].z * vv[2].y + pv[i].w * vv[3].y;
                acc[i][2] += pv[i].x * vv[0].z + pv[i].y * vv[1].z + pv[i].z * vv[2].z + pv[i].w * vv[3].z;
                acc[i][3] += pv[i].x * vv[0].w + pv[i].y * vv[1].w + pv[i].z * vv[2].w + pv[i].w * vv[3].w;
            }
        }
    }

    // epilogue: O[b, qb+i, h*64 + d] = acc / l
    float* og = O + ((size_t)(b * N_ + qb)) * C_ + h * HD_;
#pragma unroll
    for (int i = 0; i < 4; i++) {
        float inv = 1.f / l_[i];
        float4 v;
        v.x = acc[i][0] * inv; v.y = acc[i][1] * inv;
        v.z = acc[i][2] * inv; v.w = acc[i][3] * inv;
        *reinterpret_cast<float4*>(og + (size_t)(4 * ty + i) * C_ + 4 * tx) = v;
    }
}

// ---------------- launch ----------------
extern "C" void kernel_launch(void* const* d_in, const int* in_sizes, int n_in,
                              void* d_out, int out_size) {
    const float* x      = (const float*)d_in[0];
    const float* q_w    = (const float*)d_in[1];
    const float* kv_w   = (const float*)d_in[2];
    const float* sr_w   = (const float*)d_in[3];
    const float* sr_b   = (const float*)d_in[4];
    const float* proj_w = (const float*)d_in[5];
    const float* proj_b = (const float*)d_in[6];
    float* out = (float*)d_out;

    float *q, *xr, *kv, *ao, *wqT, *wkvT, *wsr, *wprT;
    cudaGetSymbolAddress((void**)&q,    g_q);
    cudaGetSymbolAddress((void**)&xr,   g_xr);
    cudaGetSymbolAddress((void**)&kv,   g_kv);
    cudaGetSymbolAddress((void**)&ao,   g_ao);
    cudaGetSymbolAddress((void**)&wqT,  g_wqT);
    cudaGetSymbolAddress((void**)&wkvT, g_wkvT);
    cudaGetSymbolAddress((void**)&wsr,  g_wsr);
    cudaGetSymbolAddress((void**)&wprT, g_wprT);

    cudaFuncSetAttribute(attn_kernel, cudaFuncAttributeMaxDynamicSharedMemorySize, ATTN_SMEM);

    // weight prep
    transpose_k<<<dim3(C_ / 32, C_ / 32), dim3(32, 8)>>>(q_w, wqT, C_, C_);
    transpose_k<<<dim3(C_ / 32, (2 * C_) / 32), dim3(32, 8)>>>(kv_w, wkvT, 2 * C_, C_);
    transpose_k<<<dim3(C_ / 32, C_ / 32), dim3(32, 8)>>>(proj_w, wprT, C_, C_);
    reorder_sr<<<(KCONV * C_) / 256, 256>>>(sr_w, wsr);

    // q projection: [B*N, C] = x @ q_w^T
    gemm128<0><<<dim3(C_ / 128, (B_ * N_) / 128), 256>>>(x, wqT, nullptr, q,
                                                         B_ * N_, C_, C_);
    // SR conv as GEMM: [B*Nk, C] (+sr_b)
    gemm128<1><<<dim3(C_ / 128, (B_ * NK_) / 128), 256>>>(x, wsr, sr_b, xr,
                                                          B_ * NK_, C_, KCONV);
    // kv projection: [B*Nk, 2C]
    gemm128<0><<<dim3((2 * C_) / 128, (B_ * NK_) / 128), 256>>>(xr, wkvT, nullptr, kv,
                                                                B_ * NK_, 2 * C_, C_);
    // fused attention
    attn_kernel<<<dim3(N_ / 64, NH_, B_), 256, ATTN_SMEM>>>(q, kv, ao);

    // output projection (+proj_b) directly into d_out
    gemm128<0><<<dim3(C_ / 128, (B_ * N_) / 128), 256>>>(ao, wprT, proj_b, out,
                                                         B_ * N_, C_, C_);
}

// round 3
// speedup vs baseline: 1.0000x; 1.0000x over previous
#include <cuda_runtime.h>
#include <cuda_bf16.h>
#include <math.h>

// Problem constants
#define B_   4
#define N_   4096
#define C_   512
#define NH_  8
#define HD_  64
#define NK_  1024   // (64/2)*(64/2)
#define KCONV 2048  // C*SR*SR

// ---------------- scratch (device globals; no runtime allocation) ----------------
__device__ float g_q  [B_ * N_  * C_];        // q projection   [B,N,C]  (c = h*64+d)
__device__ float g_xr [B_ * NK_ * C_];        // reduced x      [B,Nk,C]
__device__ float g_kv [B_ * NK_ * 2 * C_];    // kv projection  [B,Nk,2C]
__device__ float g_ao [B_ * N_  * C_];        // attention out  [B,N,C]
__device__ float g_wqT [C_ * C_];             // q_w^T     [K=512][N=512]
__device__ float g_wkvT[C_ * 2 * C_];         // kv_w^T    [K=512][N=1024]
__device__ float g_wsr [KCONV * C_];          // sr_w reord[K=2048][N=512], k=ij*512+ci
__device__ float g_wprT[C_ * C_];             // proj_w^T  [K=512][N=512]

// ---------------- weight transpose: w[Nr][Kc] -> wt[Kc][Nr] ----------------
__global__ void transpose_k(const float* __restrict__ w, float* __restrict__ wt,
                            int Nr, int Kc) {
    __shared__ float t[32][33];
    int k0 = blockIdx.x * 32, n0 = blockIdx.y * 32;
    int x = threadIdx.x, y = threadIdx.y;   // 32 x 8
#pragma unroll
    for (int yy = y; yy < 32; yy += 8)
        t[yy][x] = w[(size_t)(n0 + yy) * Kc + k0 + x];
    __syncthreads();
#pragma unroll
    for (int yy = y; yy < 32; yy += 8)
        wt[(size_t)(k0 + yy) * Nr + n0 + x] = t[x][yy];
}

// sr_w[n][ci][i][j]  ->  wsr[(ij*512+ci)*512 + n]
__global__ void reorder_sr(const float* __restrict__ w, float* __restrict__ wt) {
    int idx = blockIdx.x * 256 + threadIdx.x;     // over 2048*512
    if (idx >= KCONV * C_) return;
    int k = idx >> 9;          // /512 -> k index
    int n = idx & 511;
    int ij = k >> 9;           // k = ij*512 + ci
    int ci = k & 511;
    wt[idx] = w[(size_t)n * KCONV + ci * 4 + ij];
}

// ---------------- fp32 SGEMM: C[M,N] = A @ B' (+bias), B' is [K][N] ----------------
// 128x128 tile, KT=16, 256 threads, 8x8 per thread.
// MODE 0: A[m][k] row-major.  MODE 1: conv gather (m->(b,p), k=ij*512+ci).
template <int MODE>
__global__ __launch_bounds__(256)
void gemm128(const float* __restrict__ A, const float* __restrict__ Bm,
             const float* __restrict__ bias, float* __restrict__ Cc,
             int M, int N, int K) {
    __shared__ float As[16][132];   // transposed: As[kk][m], pad kills store conflicts
    __shared__ float Bs[16][128];   // Bs[kk][n]

    const int tid = threadIdx.x;
    const int tx = tid & 15, ty = tid >> 4;
    const int bx = blockIdx.x * 128, by = blockIdx.y * 128;

    float acc[8][8];
#pragma unroll
    for (int i = 0; i < 8; i++)
#pragma unroll
        for (int j = 0; j < 8; j++) acc[i][j] = 0.f;

    const int a_row  = tid >> 2;          // 0..63 (two passes of 64 rows)
    const int a_col4 = (tid & 3) << 2;    // 0,4,8,12
    const int b_k    = tid >> 5;          // 0..7 (two passes)
    const int b_n4   = (tid & 31) << 2;   // 0..124

    for (int k0 = 0; k0 < K; k0 += 16) {
#pragma unroll
        for (int p = 0; p < 2; p++) {
            int m = by + a_row + p * 64;
            int k = k0 + a_col4;
            size_t off;
            if (MODE == 0) {
                off = (size_t)m * K + k;
            } else {
                int bb = m >> 10;  int pp = m & 1023;
                int ph = pp >> 5;  int pw = pp & 31;
                int ij = k >> 9;   int ci = k & 511;
                int i = ij >> 1,   j = ij & 1;
                int pix = (2 * ph + i) * 64 + (2 * pw + j);
                off = ((size_t)bb * N_ + pix) * C_ + ci;
            }
            float4 v = *reinterpret_cast<const float4*>(A + off);
            As[a_col4 + 0][a_row + p * 64] = v.x;
            As[a_col4 + 1][a_row + p * 64] = v.y;
            As[a_col4 + 2][a_row + p * 64] = v.z;
            As[a_col4 + 3][a_row + p * 64] = v.w;
        }
#pragma unroll
        for (int p = 0; p < 2; p++) {
            int k = b_k + p * 8;
            float4 v = *reinterpret_cast<const float4*>(Bm + (size_t)(k0 + k) * N + bx + b_n4);
            *reinterpret_cast<float4*>(&Bs[k][b_n4]) = v;
        }
        __syncthreads();

#pragma unroll
        for (int kk = 0; kk < 16; kk++) {
            float a[8], b[8];
            *(float4*)&a[0] = *(float4*)&As[kk][ty * 8];
            *(float4*)&a[4] = *(float4*)&As[kk][ty * 8 + 4];
            *(float4*)&b[0] = *(float4*)&Bs[kk][tx * 8];
            *(float4*)&b[4] = *(float4*)&Bs[kk][tx * 8 + 4];
#pragma unroll
            for (int i = 0; i < 8; i++)
#pragma unroll
                for (int j = 0; j < 8; j++)
                    acc[i][j] += a[i] * b[j];
        }
        __syncthreads();
    }

#pragma unroll
    for (int i = 0; i < 8; i++) {
        int m = by + ty * 8 + i;
#pragma unroll
        for (int j = 0; j < 8; j += 4) {
            int n = bx + tx * 8 + j;
            float4 v;
            v.x = acc[i][j];     v.y = acc[i][j + 1];
            v.z = acc[i][j + 2]; v.w = acc[i][j + 3];
            if (bias) {
                v.x += bias[n];     v.y += bias[n + 1];
                v.z += bias[n + 2]; v.w += bias[n + 3];
            }
            *reinterpret_cast<float4*>(Cc + (size_t)m * N + n) = v;
        }
    }
}

// ---------------- fused attention (flash-style, fp32) ----------------
// grid: (N/64, nh, B); 256 threads. Per block: 64 queries of one (b,h).
// Thread (tx,ty) owns rows i=4ty+ii; S cols j=tx+16q; out cols d=4tx+jj.
#define ATTN_SMEM ((64*64 + 64*68 + 64*64 + 64*64) * 4)

__global__ __launch_bounds__(256)
void attn_kernel(const float* __restrict__ Q, const float* __restrict__ KV,
                 float* __restrict__ O) {
    extern __shared__ float sm[];
    float* Qs = sm;                // [64][64]
    float* Ks = Qs + 64 * 64;      // [64][68]  (pad 68 -> conflict-free strided reads)
    float* Vs = Ks + 64 * 68;      // [64][64]
    float* Ps = Vs + 64 * 64;      // [64][64]

    const int tid = threadIdx.x;
    const int tx = tid & 15, ty = tid >> 4;
    const int qb = blockIdx.x * 64;
    const int h  = blockIdx.y;
    const int b  = blockIdx.z;
    const float scale = 0.125f;    // hd^-0.5

    // load Q tile [64 rows][64 dims]
    const float* qg = Q + ((size_t)(b * N_ + qb)) * C_ + h * HD_;
#pragma unroll
    for (int r = 0; r < 4; r++) {
        int idx = tid + r * 256;                  // float4 slot
        int row = idx >> 4, c4 = (idx & 15) << 2;
        float4 v = *reinterpret_cast<const float4*>(qg + (size_t)row * C_ + c4);
        *reinterpret_cast<float4*>(Qs + row * 64 + c4) = v;
    }

    float m_[4], l_[4], acc[4][4];
#pragma unroll
    for (int i = 0; i < 4; i++) {
        m_[i] = -1e30f; l_[i] = 0.f;
#pragma unroll
        for (int j = 0; j < 4; j++) acc[i][j] = 0.f;
    }

    const float* kvg = KV + (size_t)b * NK_ * (2 * C_);

    for (int t = 0; t < NK_ / 64; t++) {
        __syncthreads();
        int p0 = t * 64;
#pragma unroll
        for (int r = 0; r < 4; r++) {
            int idx = tid + r * 256;
            int row = idx >> 4, c4 = (idx & 15) << 2;
            const float* base = kvg + (size_t)(p0 + row) * (2 * C_) + h * HD_ + c4;
            float4 kvec = *reinterpret_cast<const float4*>(base);
            float4 vvec = *reinterpret_cast<const float4*>(base + C_);
            *reinterpret_cast<float4*>(Ks + row * 68 + c4) = kvec;
            *reinterpret_cast<float4*>(Vs + row * 64 + c4) = vvec;
        }
        __syncthreads();

        // S = Q K^T   (rows 4ty+i, cols tx+16q)
        float s[4][4];
#pragma unroll
        for (int i = 0; i < 4; i++)
#pragma unroll
            for (int q = 0; q < 4; q++) s[i][q] = 0.f;

#pragma unroll
        for (int d = 0; d < 64; d += 4) {
            float4 qv[4], kv4[4];
#pragma unroll
            for (int i = 0; i < 4; i++)
                qv[i] = *reinterpret_cast<float4*>(Qs + (4 * ty + i) * 64 + d);
#pragma unroll
            for (int q = 0; q < 4; q++)
                kv4[q] = *reinterpret_cast<float4*>(Ks + (tx + 16 * q) * 68 + d);
#pragma unroll
            for (int i = 0; i < 4; i++)
#pragma unroll
                for (int q = 0; q < 4; q++)
                    s[i][q] += qv[i].x * kv4[q].x + qv[i].y * kv4[q].y +
                               qv[i].z * kv4[q].z + qv[i].w * kv4[q].w;
        }

        // online softmax update per row
#pragma unroll
        for (int i = 0; i < 4; i++) {
#pragma unroll
            for (int q = 0; q < 4; q++) s[i][q] *= scale;
            float mx = fmaxf(fmaxf(s[i][0], s[i][1]), fmaxf(s[i][2], s[i][3]));
#pragma unroll
            for (int o = 8; o >= 1; o >>= 1)
                mx = fmaxf(mx, __shfl_xor_sync(0xffffffffu, mx, o));
            float mn = fmaxf(m_[i], mx);
            float al = __expf(m_[i] - mn);
            float p[4], sum = 0.f;
#pragma unroll
            for (int q = 0; q < 4; q++) { p[q] = __expf(s[i][q] - mn); sum += p[q]; }
#pragma unroll
            for (int o = 8; o >= 1; o >>= 1)
                sum += __shfl_xor_sync(0xffffffffu, sum, o);
            l_[i] = l_[i] * al + sum;
            m_[i] = mn;
#pragma unroll
            for (int j = 0; j < 4; j++) acc[i][j] *= al;
#pragma unroll
            for (int q = 0; q < 4; q++)
                Ps[(4 * ty + i) * 64 + tx + 16 * q] = p[q];
        }
        __syncthreads();

        // acc += P @ V   (out cols 4tx+jj)
#pragma unroll
        for (int j0 = 0; j0 < 64; j0 += 4) {
            float4 pv[4], vv[4];
#pragma unroll
            for (int i = 0; i < 4; i++)
                pv[i] = *reinterpret_cast<float4*>(Ps + (4 * ty + i) * 64 + j0);
#pragma unroll
            for (int q = 0; q < 4; q++)
                vv[q] = *reinterpret_cast<float4*>(Vs + (j0 + q) * 64 + 4 * tx);
#pragma unroll
            for (int i = 0; i < 4; i++) {
                acc[i][0] += pv[i].x * vv[0].x + pv[i].y * vv[1].x + pv[i].z * vv[2].x + pv[i].w * vv[3].x;
                acc[i][1] += pv[i].x * vv[0].y + pv[i].y * vv[1].y + pv[i].z * vv[2].y + pv[i].w * vv[3].y;
                acc[i][2] += pv[i].x * vv[0].z + pv[i].y * vv[1].z + pv[i].z * vv[2].z + pv[i].w * vv[3].z;
                acc[i][3] += pv[i].x * vv[0].w + pv[i].y * vv[1].w + pv[i].z * vv[2].w + pv[i].w * vv[3].w;
            }
        }
    }

    // epilogue: O[b, qb+i, h*64 + d] = acc / l
    float* og = O + ((size_t)(b * N_ + qb)) * C_ + h * HD_;
#pragma unroll
    for (int i = 0; i < 4; i++) {
        float inv = 1.f / l_[i];
        float4 v;
        v.x = acc[i][0] * inv; v.y = acc[i][1] * inv;
        v.z = acc[i][2] * inv; v.w = acc[i][3] * inv;
        *reinterpret_cast<float4*>(og + (size_t)(4 * ty + i) * C_ + 4 * tx) = v;
    }
}

// ---------------- launch ----------------
extern "C" void kernel_launch(void* const* d_in, const int* in_sizes, int n_in,
                              void* d_out, int out_size) {
    const float* x      = (const float*)d_in[0];
    const float* q_w    = (const float*)d_in[1];
    const float* kv_w   = (const float*)d_in[2];
    const float* sr_w   = (const float*)d_in[3];
    const float* sr_b   = (const float*)d_in[4];
    const float* proj_w = (const float*)d_in[5];
    const float* proj_b = (const float*)d_in[6];
    float* out = (float*)d_out;

    float *q, *xr, *kv, *ao, *wqT, *wkvT, *wsr, *wprT;
    cudaGetSymbolAddress((void**)&q,    g_q);
    cudaGetSymbolAddress((void**)&xr,   g_xr);
    cudaGetSymbolAddress((void**)&kv,   g_kv);
    cudaGetSymbolAddress((void**)&ao,   g_ao);
    cudaGetSymbolAddress((void**)&wqT,  g_wqT);
    cudaGetSymbolAddress((void**)&wkvT, g_wkvT);
    cudaGetSymbolAddress((void**)&wsr,  g_wsr);
    cudaGetSymbolAddress((void**)&wprT, g_wprT);

    cudaFuncSetAttribute(attn_kernel, cudaFuncAttributeMaxDynamicSharedMemorySize, ATTN_SMEM);

    // weight prep
    transpose_k<<<dim3(C_ / 32, C_ / 32), dim3(32, 8)>>>(q_w, wqT, C_, C_);
    transpose_k<<<dim3(C_ / 32, (2 * C_) / 32), dim3(32, 8)>>>(kv_w, wkvT, 2 * C_, C_);
    transpose_k<<<dim3(C_ / 32, C_ / 32), dim3(32, 8)>>>(proj_w, wprT, C_, C_);
    reorder_sr<<<(KCONV * C_) / 256, 256>>>(sr_w, wsr);

    // q projection: [B*N, C] = x @ q_w^T
    gemm128<0><<<dim3(C_ / 128, (B_ * N_) / 128), 256>>>(x, wqT, nullptr, q,
                                                         B_ * N_, C_, C_);
    // SR conv as GEMM: [B*Nk, C] (+sr_b)
    gemm128<1><<<dim3(C_ / 128, (B_ * NK_) / 128), 256>>>(x, wsr, sr_b, xr,
                                                          B_ * NK_, C_, KCONV);
    // kv projection: [B*Nk, 2C]
    gemm128<0><<<dim3((2 * C_) / 128, (B_ * NK_) / 128), 256>>>(xr, wkvT, nullptr, kv,
                                                                B_ * NK_, 2 * C_, C_);
    // fused attention
    attn_kernel<<<dim3(N_ / 64, NH_, B_), 256, ATTN_SMEM>>>(q, kv, ao);

    // output projection (+proj_b) directly into d_out
    gemm128<0><<<dim3(C_ / 128, (B_ * N_) / 128), 256>>>(ao, wprT, proj_b, out,
                                                         B_ * N_, C_, C_);
}

// round 6
// speedup vs baseline: 1.0470x; 1.0470x over previous
#include <cuda_runtime.h>
#include <cuda_bf16.h>
#include <cstdint>

#define B_   4
#define N_   4096
#define C_   512
#define NK_  1024
#define KCONV 2048
typedef unsigned long long u64;

// ---------------- scratch ----------------
__device__ float g_q  [B_ * N_  * C_];
__device__ float g_xr [B_ * NK_ * C_];
__device__ float g_kv [B_ * NK_ * 2 * C_];
__device__ float g_ao [B_ * N_  * C_];
__device__ float g_wqT [C_ * C_];
__device__ float g_wkvT[C_ * 2 * C_];
__device__ float g_wsr [KCONV * C_];
__device__ float g_wprT[C_ * C_];

// ---------------- packed f32x2 helpers ----------------
__device__ __forceinline__ u64 pk2(float a, float b){
    u64 r; asm("mov.b64 %0, {%1,%2};" : "=l"(r) : "f"(a), "f"(b)); return r;
}
__device__ __forceinline__ void fma2(u64& d, u64 a, u64 b){
    asm("fma.rn.f32x2 %0, %1, %2, %0;" : "+l"(d) : "l"(a), "l"(b));
}
__device__ __forceinline__ void mul2(u64& d, u64 a){
    asm("mul.rn.f32x2 %0, %0, %1;" : "+l"(d) : "l"(a));
}
__device__ __forceinline__ float2 up2(u64 v){
    float2 f; asm("mov.b64 {%0,%1}, %2;" : "=f"(f.x), "=f"(f.y) : "l"(v)); return f;
}
union f4u { float4 f; u64 d[2]; };

// ---------------- weight transpose: w[Nr][Kc] -> wt[Kc][Nr] ----------------
__global__ void transpose_k(const float* __restrict__ w, float* __restrict__ wt,
                            int Nr, int Kc) {
    __shared__ float t[32][33];
    int k0 = blockIdx.x * 32, n0 = blockIdx.y * 32;
    int x = threadIdx.x, y = threadIdx.y;   // 32 x 8
#pragma unroll
    for (int yy = y; yy < 32; yy += 8)
        t[yy][x] = w[(size_t)(n0 + yy) * Kc + k0 + x];
    __syncthreads();
#pragma unroll
    for (int yy = y; yy < 32; yy += 8)
        wt[(size_t)(k0 + yy) * Nr + n0 + x] = t[x][yy];
}

// sr_w[n][ci][i][j]  ->  wsr[(ij*512+ci)*512 + n]
__global__ void reorder_sr(const float* __restrict__ w, float* __restrict__ wt) {
    int idx = blockIdx.x * 256 + threadIdx.x;
    if (idx >= KCONV * C_) return;
    int k = idx >> 9;
    int n = idx & 511;
    int ij = k >> 9;
    int ci = k & 511;
    wt[idx] = w[(size_t)n * KCONV + ci * 4 + ij];
}

// ---------------- fp32 SGEMM with packed FFMA2 ----------------
// 128x128 tile, KT=16, 256 threads, 8x8 per thread (4 u64 col-pairs).
template <int MODE>
__global__ __launch_bounds__(256)
void gemm128(const float* __restrict__ A, const float* __restrict__ Bm,
             const float* __restrict__ bias, float* __restrict__ Cc,
             int M, int N, int K) {
    __shared__ float As[16][132];
    __shared__ float Bs[16][128];

    const int tid = threadIdx.x;
    const int tx = tid & 15, ty = tid >> 4;
    const int bx = blockIdx.x * 128, by = blockIdx.y * 128;

    u64 acc2[8][4];
#pragma unroll
    for (int i = 0; i < 8; i++)
#pragma unroll
        for (int j = 0; j < 4; j++) acc2[i][j] = 0ull;

    const int a_row  = tid >> 2;
    const int a_col4 = (tid & 3) << 2;
    const int b_k    = tid >> 5;
    const int b_n4   = (tid & 31) << 2;

    for (int k0 = 0; k0 < K; k0 += 16) {
#pragma unroll
        for (int p = 0; p < 2; p++) {
            int m = by + a_row + p * 64;
            int k = k0 + a_col4;
            size_t off;
            if (MODE == 0) {
                off = (size_t)m * K + k;
            } else {
                int bb = m >> 10;  int pp = m & 1023;
                int ph = pp >> 5;  int pw = pp & 31;
                int ij = k >> 9;   int ci = k & 511;
                int i = ij >> 1,   j = ij & 1;
                int pix = (2 * ph + i) * 64 + (2 * pw + j);
                off = ((size_t)bb * N_ + pix) * C_ + ci;
            }
            float4 v = *reinterpret_cast<const float4*>(A + off);
            As[a_col4 + 0][a_row + p * 64] = v.x;
            As[a_col4 + 1][a_row + p * 64] = v.y;
            As[a_col4 + 2][a_row + p * 64] = v.z;
            As[a_col4 + 3][a_row + p * 64] = v.w;
        }
#pragma unroll
        for (int p = 0; p < 2; p++) {
            int k = b_k + p * 8;
            float4 v = *reinterpret_cast<const float4*>(Bm + (size_t)(k0 + k) * N + bx + b_n4);
            *reinterpret_cast<float4*>(&Bs[k][b_n4]) = v;
        }
        __syncthreads();

#pragma unroll
        for (int kk = 0; kk < 16; kk++) {
            float a[8];
            f4u b0, b1;
            *(float4*)&a[0] = *(float4*)&As[kk][ty * 8];
            *(float4*)&a[4] = *(float4*)&As[kk][ty * 8 + 4];
            b0.f = *(float4*)&Bs[kk][tx * 8];
            b1.f = *(float4*)&Bs[kk][tx * 8 + 4];
#pragma unroll
            for (int i = 0; i < 8; i++) {
                u64 ap = pk2(a[i], a[i]);
                fma2(acc2[i][0], ap, b0.d[0]);
                fma2(acc2[i][1], ap, b0.d[1]);
                fma2(acc2[i][2], ap, b1.d[0]);
                fma2(acc2[i][3], ap, b1.d[1]);
            }
        }
        __syncthreads();
    }

#pragma unroll
    for (int i = 0; i < 8; i++) {
        int m = by + ty * 8 + i;
#pragma unroll
        for (int jp = 0; jp < 4; jp += 2) {
            int n = bx + tx * 8 + jp * 2;
            float2 p0 = up2(acc2[i][jp]);
            float2 p1 = up2(acc2[i][jp + 1]);
            float4 v;
            v.x = p0.x; v.y = p0.y; v.z = p1.x; v.w = p1.y;
            if (bias) {
                v.x += bias[n];     v.y += bias[n + 1];
                v.z += bias[n + 2]; v.w += bias[n + 3];
            }
            *reinterpret_cast<float4*>(Cc + (size_t)m * N + n) = v;
        }
    }
}

// ---------------- fused attention (flash-style, packed FFMA2) ----------------
#define ATTN_SMEM ((64*64 + 64*68 + 64*64 + 64*64) * 4)

__global__ __launch_bounds__(256)
void attn_kernel(const float* __restrict__ Q, const float* __restrict__ KV,
                 float* __restrict__ O) {
    extern __shared__ float sm[];
    float* Qs = sm;                // [64][64]
    float* Ks = Qs + 64 * 64;      // [64][68]
    float* Vs = Ks + 64 * 68;      // [64][64]
    float* Ps = Vs + 64 * 64;      // [64][64]

    const int tid = threadIdx.x;
    const int tx = tid & 15, ty = tid >> 4;
    const int qb = blockIdx.x * 64;
    const int h  = blockIdx.y;
    const int b  = blockIdx.z;
    const float scale = 0.125f;

    const float* qg = Q + ((size_t)(b * N_ + qb)) * C_ + h * 64;
#pragma unroll
    for (int r = 0; r < 4; r++) {
        int idx = tid + r * 256;
        int row = idx >> 4, c4 = (idx & 15) << 2;
        *reinterpret_cast<float4*>(Qs + row * 64 + c4) =
            *reinterpret_cast<const float4*>(qg + (size_t)row * C_ + c4);
    }

    float m_[4], l_[4];
    u64 acc2[4][2];
#pragma unroll
    for (int i = 0; i < 4; i++) {
        m_[i] = -1e30f; l_[i] = 0.f;
        acc2[i][0] = 0ull; acc2[i][1] = 0ull;
    }
    const float* kvg = KV + (size_t)b * NK_ * (2 * C_);

    for (int t = 0; t < NK_ / 64; t++) {
        __syncthreads();
        int p0 = t * 64;
#pragma unroll
        for (int r = 0; r < 4; r++) {
            int idx = tid + r * 256;
            int row = idx >> 4, c4 = (idx & 15) << 2;
            const float* base = kvg + (size_t)(p0 + row) * (2 * C_) + h * 64 + c4;
            *reinterpret_cast<float4*>(Ks + row * 68 + c4) = *reinterpret_cast<const float4*>(base);
            *reinterpret_cast<float4*>(Vs + row * 64 + c4) = *reinterpret_cast<const float4*>(base + C_);
        }
        __syncthreads();

        // S = Q K^T  (rows 4ty+i, cols tx+16q), packed over d
        u64 sp[4][4];
#pragma unroll
        for (int i = 0; i < 4; i++)
#pragma unroll
            for (int q = 0; q < 4; q++) sp[i][q] = 0ull;
#pragma unroll
        for (int d = 0; d < 64; d += 4) {
            f4u qv[4], kv4[4];
#pragma unroll
            for (int i = 0; i < 4; i++)
                qv[i].f = *reinterpret_cast<float4*>(Qs + (4 * ty + i) * 64 + d);
#pragma unroll
            for (int q = 0; q < 4; q++)
                kv4[q].f = *reinterpret_cast<float4*>(Ks + (tx + 16 * q) * 68 + d);
#pragma unroll
            for (int i = 0; i < 4; i++)
#pragma unroll
                for (int q = 0; q < 4; q++) {
                    fma2(sp[i][q], qv[i].d[0], kv4[q].d[0]);
                    fma2(sp[i][q], qv[i].d[1], kv4[q].d[1]);
                }
        }

        // online softmax
#pragma unroll
        for (int i = 0; i < 4; i++) {
            float s[4];
#pragma unroll
            for (int q = 0; q < 4; q++) {
                float2 f = up2(sp[i][q]);
                s[q] = (f.x + f.y) * scale;
            }
            float mx = fmaxf(fmaxf(s[0], s[1]), fmaxf(s[2], s[3]));
#pragma unroll
            for (int o = 8; o >= 1; o >>= 1)
                mx = fmaxf(mx, __shfl_xor_sync(0xffffffffu, mx, o));
            float mn = fmaxf(m_[i], mx);
            float al = __expf(m_[i] - mn);
            float p[4], sum = 0.f;
#pragma unroll
            for (int q = 0; q < 4; q++) { p[q] = __expf(s[q] - mn); sum += p[q]; }
#pragma unroll
            for (int o = 8; o >= 1; o >>= 1)
                sum += __shfl_xor_sync(0xffffffffu, sum, o);
            l_[i] = l_[i] * al + sum;
            m_[i] = mn;
            u64 al2 = pk2(al, al);
            mul2(acc2[i][0], al2);
            mul2(acc2[i][1], al2);
#pragma unroll
            for (int q = 0; q < 4; q++)
                Ps[(4 * ty + i) * 64 + tx + 16 * q] = p[q];
        }
        __syncthreads();

        // acc += P @ V  (out cols 4tx..4tx+3, two packed pairs)
#pragma unroll
        for (int j0 = 0; j0 < 64; j0 += 4) {
            f4u pv[4], vv[4];
#pragma unroll
            for (int i = 0; i < 4; i++)
                pv[i].f = *reinterpret_cast<float4*>(Ps + (4 * ty + i) * 64 + j0);
#pragma unroll
            for (int q = 0; q < 4; q++)
                vv[q].f = *reinterpret_cast<float4*>(Vs + (j0 + q) * 64 + 4 * tx);
#pragma unroll
            for (int i = 0; i < 4; i++) {
                const float* pe = reinterpret_cast<const float*>(&pv[i].f);
#pragma unroll
                for (int q = 0; q < 4; q++) {
                    u64 pq = pk2(pe[q], pe[q]);
                    fma2(acc2[i][0], pq, vv[q].d[0]);
                    fma2(acc2[i][1], pq, vv[q].d[1]);
                }
            }
        }
    }

    float* og = O + ((size_t)(b * N_ + qb)) * C_ + h * 64;
#pragma unroll
    for (int i = 0; i < 4; i++) {
        float inv = 1.f / l_[i];
        float2 a0 = up2(acc2[i][0]), a1 = up2(acc2[i][1]);
        float4 v;
        v.x = a0.x * inv; v.y = a0.y * inv; v.z = a1.x * inv; v.w = a1.y * inv;
        *reinterpret_cast<float4*>(og + (size_t)(4 * ty + i) * C_ + 4 * tx) = v;
    }
}

// ---------------- launch ----------------
extern "C" void kernel_launch(void* const* d_in, const int* in_sizes, int n_in,
                              void* d_out, int out_size) {
    const float* x      = (const float*)d_in[0];
    const float* q_w    = (const float*)d_in[1];
    const float* kv_w   = (const float*)d_in[2];
    const float* sr_w   = (const float*)d_in[3];
    const float* sr_b   = (const float*)d_in[4];
    const float* proj_w = (const float*)d_in[5];
    const float* proj_b = (const float*)d_in[6];
    float* out = (float*)d_out;

    float *q, *xr, *kv, *ao, *wqT, *wkvT, *wsr, *wprT;
    cudaGetSymbolAddress((void**)&q,    g_q);
    cudaGetSymbolAddress((void**)&xr,   g_xr);
    cudaGetSymbolAddress((void**)&kv,   g_kv);
    cudaGetSymbolAddress((void**)&ao,   g_ao);
    cudaGetSymbolAddress((void**)&wqT,  g_wqT);
    cudaGetSymbolAddress((void**)&wkvT, g_wkvT);
    cudaGetSymbolAddress((void**)&wsr,  g_wsr);
    cudaGetSymbolAddress((void**)&wprT, g_wprT);

    cudaFuncSetAttribute(attn_kernel, cudaFuncAttributeMaxDynamicSharedMemorySize, ATTN_SMEM);

    transpose_k<<<dim3(C_ / 32, C_ / 32), dim3(32, 8)>>>(q_w, wqT, C_, C_);
    transpose_k<<<dim3(C_ / 32, (2 * C_) / 32), dim3(32, 8)>>>(kv_w, wkvT, 2 * C_, C_);
    transpose_k<<<dim3(C_ / 32, C_ / 32), dim3(32, 8)>>>(proj_w, wprT, C_, C_);
    reorder_sr<<<(KCONV * C_) / 256, 256>>>(sr_w, wsr);

    gemm128<0><<<dim3(C_ / 128, (B_ * N_) / 128), 256>>>(x, wqT, nullptr, q,
                                                         B_ * N_, C_, C_);
    gemm128<1><<<dim3(C_ / 128, (B_ * NK_) / 128), 256>>>(x, wsr, sr_b, xr,
                                                          B_ * NK_, C_, KCONV);
    gemm128<0><<<dim3((2 * C_) / 128, (B_ * NK_) / 128), 256>>>(xr, wkvT, nullptr, kv,
                                                                B_ * NK_, 2 * C_, C_);
    attn_kernel<<<dim3(N_ / 64, 8, B_), 256, ATTN_SMEM>>>(q, kv, ao);
    gemm128<0><<<dim3(C_ / 128, (B_ * N_) / 128), 256>>>(ao, wprT, proj_b, out,
                                                         B_ * N_, C_, C_);
}

// round 7
// speedup vs baseline: 1.2999x; 1.2415x over previous
#include <cuda_runtime.h>
#include <cuda_bf16.h>
#include <cstdint>

#define B_   4
#define N_   4096
#define C_   512
#define NK_  1024
#define KCONV 2048
typedef unsigned long long u64;

// ---------------- scratch ----------------
__device__ float g_q  [B_ * N_  * C_];
__device__ float g_xr [B_ * NK_ * C_];
__device__ float g_kv [B_ * NK_ * 2 * C_];
__device__ float g_ao [B_ * N_  * C_];
__device__ float g_wsr [C_ * KCONV];   // sr_w reordered: [n][k'], k' = ij*512 + ci

// ---------------- packed f32x2 helpers (attention) ----------------
__device__ __forceinline__ u64 pk2(float a, float b){
    u64 r; asm("mov.b64 %0, {%1,%2};" : "=l"(r) : "f"(a), "f"(b)); return r;
}
__device__ __forceinline__ void fma2(u64& d, u64 a, u64 b){
    asm("fma.rn.f32x2 %0, %1, %2, %0;" : "+l"(d) : "l"(a), "l"(b));
}
__device__ __forceinline__ void mul2(u64& d, u64 a){
    asm("mul.rn.f32x2 %0, %0, %1;" : "+l"(d) : "l"(a));
}
__device__ __forceinline__ float2 up2(u64 v){
    float2 f; asm("mov.b64 {%0,%1}, %2;" : "=f"(f.x), "=f"(f.y) : "l"(v)); return f;
}
union f4u { float4 f; u64 d[2]; };

// ---------------- mma / split helpers ----------------
__device__ __forceinline__ void mma16816(float* c, const uint32_t* a, const uint32_t* b){
    asm volatile("mma.sync.aligned.m16n8k16.row.col.f32.bf16.bf16.f32 "
        "{%0,%1,%2,%3}, {%4,%5,%6,%7}, {%8,%9}, {%0,%1,%2,%3};"
        : "+f"(c[0]), "+f"(c[1]), "+f"(c[2]), "+f"(c[3])
        : "r"(a[0]), "r"(a[1]), "r"(a[2]), "r"(a[3]), "r"(b[0]), "r"(b[1]));
}
// split (x,y) fp32 pair into packed bf16x2 hi and lo
__device__ __forceinline__ void split2(float x, float y, uint32_t& h, uint32_t& l){
    __nv_bfloat162 hh = __float22bfloat162_rn(make_float2(x, y));
    float2 hf = __bfloat1622float2(hh);
    __nv_bfloat162 ll = __float22bfloat162_rn(make_float2(x - hf.x, y - hf.y));
    h = *(uint32_t*)&hh; l = *(uint32_t*)&ll;
}

// sr_w[n][ci][i][j] -> wsr[n][k'], k' = ij*512 + ci  (keeps A-gather float4-contiguous in ci)
__global__ void reorder_sr(const float* __restrict__ w, float* __restrict__ wt) {
    int idx = blockIdx.x * 256 + threadIdx.x;       // over 512*2048
    int n = idx >> 11, k = idx & 2047;
    int ij = k >> 9, ci = k & 511;
    wt[idx] = w[((size_t)n * C_ + ci) * 4 + ij];
}

// ---------------- tensor-core GEMM: out[M,N] = A @ B^T (+bias) ----------------
// A fp32 (row-major [m][k], or MODE1 conv gather), B fp32 [n][k] (natural weight layout).
// Internally: bf16 hi/lo 3-term (AhBh + AhBl + AlBh) via mma.sync m16n8k16.
// Block 128x128, 8 warps (2m x 4n -> warp tile 64x32), KT=32.
// SMEM rows padded to 40 bf16 (80B) -> fragment LDS.32 loads conflict-free.
template <int MODE>
__global__ __launch_bounds__(256)
void hgemm(const float* __restrict__ A, const float* __restrict__ Bw,
           const float* __restrict__ bias, float* __restrict__ out,
           int M, int N, int K) {
    __shared__ uint32_t sAh[128 * 20], sAl[128 * 20];   // [row][k/2], 40 bf16/row
    __shared__ uint32_t sBh[128 * 20], sBl[128 * 20];

    const int tid  = threadIdx.x;
    const int lane = tid & 31, warp = tid >> 5;
    const int wm = (warp >> 2) * 64, wn = (warp & 3) * 32;
    const int bx = blockIdx.x * 128, by = blockIdx.y * 128;

    float acc[4][4][4];
#pragma unroll
    for (int i = 0; i < 4; i++)
#pragma unroll
        for (int j = 0; j < 4; j++)
#pragma unroll
            for (int r = 0; r < 4; r++) acc[i][j][r] = 0.f;

    const int lrow = tid >> 1;            // 0..127
    const int lkq  = (tid & 1) * 16;      // 0 or 16

    for (int kc = 0; kc < K; kc += 32) {
        // ---- load + convert A,B chunk: 128 rows x 32 k each ----
#pragma unroll
        for (int f = 0; f < 4; f++) {
            int k = lkq + 4 * f;          // 0..28, step 4
            size_t aoff;
            if (MODE == 0) {
                aoff = (size_t)(by + lrow) * K + kc + k;
            } else {
                int m = by + lrow;
                int bb = m >> 10, pp = m & 1023, ph = pp >> 5, pw = pp & 31;
                int kg = kc + k;
                int ij = kg >> 9, ci = kg & 511;
                int pix = (2 * ph + (ij >> 1)) * 64 + 2 * pw + (ij & 1);
                aoff = ((size_t)(bb << 12) + pix) * C_ + ci;
            }
            float4 va = *reinterpret_cast<const float4*>(A + aoff);
            float4 vb = *reinterpret_cast<const float4*>(
                            Bw + (size_t)(bx + lrow) * K + kc + k);
            int u = lrow * 20 + (k >> 1);
            split2(va.x, va.y, sAh[u],     sAl[u]);
            split2(va.z, va.w, sAh[u + 1], sAl[u + 1]);
            split2(vb.x, vb.y, sBh[u],     sBl[u]);
            split2(vb.z, vb.w, sBh[u + 1], sBl[u + 1]);
        }
        __syncthreads();

        // ---- compute: 2 k16 halves x 3 terms x (4 mtiles x 4 ntiles) ----
#pragma unroll
        for (int kh = 0; kh < 2; kh++) {
            uint32_t ah[4][4], al[4][4], bh[4][2], bl[4][2];
            const int cq = kh * 8 + (lane & 3);          // u32 col within row
            const int rq = lane >> 2;
#pragma unroll
            for (int mt = 0; mt < 4; mt++) {
                int r0 = (wm + 16 * mt + rq) * 20;
                int r1 = r0 + 8 * 20;
                ah[mt][0] = sAh[r0 + cq];     ah[mt][1] = sAh[r1 + cq];
                ah[mt][2] = sAh[r0 + cq + 4]; ah[mt][3] = sAh[r1 + cq + 4];
                al[mt][0] = sAl[r0 + cq];     al[mt][1] = sAl[r1 + cq];
                al[mt][2] = sAl[r0 + cq + 4]; al[mt][3] = sAl[r1 + cq + 4];
            }
#pragma unroll
            for (int nt = 0; nt < 4; nt++) {
                int rb = (wn + 8 * nt + rq) * 20;
                bh[nt][0] = sBh[rb + cq]; bh[nt][1] = sBh[rb + cq + 4];
                bl[nt][0] = sBl[rb + cq]; bl[nt][1] = sBl[rb + cq + 4];
            }
#pragma unroll
            for (int mt = 0; mt < 4; mt++)
#pragma unroll
                for (int nt = 0; nt < 4; nt++) {
                    mma16816(acc[mt][nt], ah[mt], bh[nt]);
                    mma16816(acc[mt][nt], ah[mt], bl[nt]);
                    mma16816(acc[mt][nt], al[mt], bh[nt]);
                }
        }
        __syncthreads();
    }

    // ---- epilogue: acc frag (rows t>>2, t>>2+8; cols 2(t&3)) -> gmem fp32 ----
    const int rq = lane >> 2, cq = 2 * (lane & 3);
#pragma unroll
    for (int mt = 0; mt < 4; mt++) {
#pragma unroll
        for (int nt = 0; nt < 4; nt++) {
            int col = bx + wn + 8 * nt + cq;
            float bx0 = bias ? bias[col] : 0.f;
            float bx1 = bias ? bias[col + 1] : 0.f;
            int r0 = by + wm + 16 * mt + rq;
            float2 v0 = make_float2(acc[mt][nt][0] + bx0, acc[mt][nt][1] + bx1);
            float2 v1 = make_float2(acc[mt][nt][2] + bx0, acc[mt][nt][3] + bx1);
            *reinterpret_cast<float2*>(out + (size_t)r0 * N + col) = v0;
            *reinterpret_cast<float2*>(out + (size_t)(r0 + 8) * N + col) = v1;
        }
    }
}

// ---------------- fused attention (flash-style, packed FFMA2) ----------------
#define ATTN_SMEM ((64*64 + 64*68 + 64*64 + 64*64) * 4)

__global__ __launch_bounds__(256)
void attn_kernel(const float* __restrict__ Q, const float* __restrict__ KV,
                 float* __restrict__ O) {
    extern __shared__ float sm[];
    float* Qs = sm;
    float* Ks = Qs + 64 * 64;
    float* Vs = Ks + 64 * 68;
    float* Ps = Vs + 64 * 64;

    const int tid = threadIdx.x;
    const int tx = tid & 15, ty = tid >> 4;
    const int qb = blockIdx.x * 64;
    const int h  = blockIdx.y;
    const int b  = blockIdx.z;
    const float scale = 0.125f;

    const float* qg = Q + ((size_t)(b * N_ + qb)) * C_ + h * 64;
#pragma unroll
    for (int r = 0; r < 4; r++) {
        int idx = tid + r * 256;
        int row = idx >> 4, c4 = (idx & 15) << 2;
        *reinterpret_cast<float4*>(Qs + row * 64 + c4) =
            *reinterpret_cast<const float4*>(qg + (size_t)row * C_ + c4);
    }

    float m_[4], l_[4];
    u64 acc2[4][2];
#pragma unroll
    for (int i = 0; i < 4; i++) {
        m_[i] = -1e30f; l_[i] = 0.f;
        acc2[i][0] = 0ull; acc2[i][1] = 0ull;
    }
    const float* kvg = KV + (size_t)b * NK_ * (2 * C_);

    for (int t = 0; t < NK_ / 64; t++) {
        __syncthreads();
        int p0 = t * 64;
#pragma unroll
        for (int r = 0; r < 4; r++) {
            int idx = tid + r * 256;
            int row = idx >> 4, c4 = (idx & 15) << 2;
            const float* base = kvg + (size_t)(p0 + row) * (2 * C_) + h * 64 + c4;
            *reinterpret_cast<float4*>(Ks + row * 68 + c4) = *reinterpret_cast<const float4*>(base);
            *reinterpret_cast<float4*>(Vs + row * 64 + c4) = *reinterpret_cast<const float4*>(base + C_);
        }
        __syncthreads();

        u64 sp[4][4];
#pragma unroll
        for (int i = 0; i < 4; i++)
#pragma unroll
            for (int q = 0; q < 4; q++) sp[i][q] = 0ull;
#pragma unroll
        for (int d = 0; d < 64; d += 4) {
            f4u qv[4], kv4[4];
#pragma unroll
            for (int i = 0; i < 4; i++)
                qv[i].f = *reinterpret_cast<float4*>(Qs + (4 * ty + i) * 64 + d);
#pragma unroll
            for (int q = 0; q < 4; q++)
                kv4[q].f = *reinterpret_cast<float4*>(Ks + (tx + 16 * q) * 68 + d);
#pragma unroll
            for (int i = 0; i < 4; i++)
#pragma unroll
                for (int q = 0; q < 4; q++) {
                    fma2(sp[i][q], qv[i].d[0], kv4[q].d[0]);
                    fma2(sp[i][q], qv[i].d[1], kv4[q].d[1]);
                }
        }

#pragma unroll
        for (int i = 0; i < 4; i++) {
            float s[4];
#pragma unroll
            for (int q = 0; q < 4; q++) {
                float2 f = up2(sp[i][q]);
                s[q] = (f.x + f.y) * scale;
            }
            float mx = fmaxf(fmaxf(s[0], s[1]), fmaxf(s[2], s[3]));
#pragma unroll
            for (int o = 8; o >= 1; o >>= 1)
                mx = fmaxf(mx, __shfl_xor_sync(0xffffffffu, mx, o));
            float mn = fmaxf(m_[i], mx);
            float al = __expf(m_[i] - mn);
            float p[4], sum = 0.f;
#pragma unroll
            for (int q = 0; q < 4; q++) { p[q] = __expf(s[q] - mn); sum += p[q]; }
#pragma unroll
            for (int o = 8; o >= 1; o >>= 1)
                sum += __shfl_xor_sync(0xffffffffu, sum, o);
            l_[i] = l_[i] * al + sum;
            m_[i] = mn;
            u64 al2 = pk2(al, al);
            mul2(acc2[i][0], al2);
            mul2(acc2[i][1], al2);
#pragma unroll
            for (int q = 0; q < 4; q++)
                Ps[(4 * ty + i) * 64 + tx + 16 * q] = p[q];
        }
        __syncthreads();

#pragma unroll
        for (int j0 = 0; j0 < 64; j0 += 4) {
            f4u pv[4], vv[4];
#pragma unroll
            for (int i = 0; i < 4; i++)
                pv[i].f = *reinterpret_cast<float4*>(Ps + (4 * ty + i) * 64 + j0);
#pragma unroll
            for (int q = 0; q < 4; q++)
                vv[q].f = *reinterpret_cast<float4*>(Vs + (j0 + q) * 64 + 4 * tx);
#pragma unroll
            for (int i = 0; i < 4; i++) {
                const float* pe = reinterpret_cast<const float*>(&pv[i].f);
#pragma unroll
                for (int q = 0; q < 4; q++) {
                    u64 pq = pk2(pe[q], pe[q]);
                    fma2(acc2[i][0], pq, vv[q].d[0]);
                    fma2(acc2[i][1], pq, vv[q].d[1]);
                }
            }
        }
    }

    float* og = O + ((size_t)(b * N_ + qb)) * C_ + h * 64;
#pragma unroll
    for (int i = 0; i < 4; i++) {
        float inv = 1.f / l_[i];
        float2 a0 = up2(acc2[i][0]), a1 = up2(acc2[i][1]);
        float4 v;
        v.x = a0.x * inv; v.y = a0.y * inv; v.z = a1.x * inv; v.w = a1.y * inv;
        *reinterpret_cast<float4*>(og + (size_t)(4 * ty + i) * C_ + 4 * tx) = v;
    }
}

// ---------------- launch ----------------
extern "C" void kernel_launch(void* const* d_in, const int* in_sizes, int n_in,
                              void* d_out, int out_size) {
    const float* x      = (const float*)d_in[0];
    const float* q_w    = (const float*)d_in[1];
    const float* kv_w   = (const float*)d_in[2];
    const float* sr_w   = (const float*)d_in[3];
    const float* sr_b   = (const float*)d_in[4];
    const float* proj_w = (const float*)d_in[5];
    const float* proj_b = (const float*)d_in[6];
    float* out = (float*)d_out;

    float *q, *xr, *kv, *ao, *wsr;
    cudaGetSymbolAddress((void**)&q,   g_q);
    cudaGetSymbolAddress((void**)&xr,  g_xr);
    cudaGetSymbolAddress((void**)&kv,  g_kv);
    cudaGetSymbolAddress((void**)&ao,  g_ao);
    cudaGetSymbolAddress((void**)&wsr, g_wsr);

    cudaFuncSetAttribute(attn_kernel, cudaFuncAttributeMaxDynamicSharedMemorySize, ATTN_SMEM);

    // weight prep: only the conv filter needs reordering ([n][k'], k'=ij*512+ci)
    reorder_sr<<<(C_ * KCONV) / 256, 256>>>(sr_w, wsr);

    // q projection: [16384,512] = x @ q_w^T
    hgemm<0><<<dim3(C_ / 128, (B_ * N_) / 128), 256>>>(x, q_w, nullptr, q,
                                                       B_ * N_, C_, C_);
    // SR conv as GEMM (gathered A): [4096,512] (+sr_b)
    hgemm<1><<<dim3(C_ / 128, (B_ * NK_) / 128), 256>>>(x, wsr, sr_b, xr,
                                                        B_ * NK_, C_, KCONV);
    // kv projection: [4096,1024]
    hgemm<0><<<dim3((2 * C_) / 128, (B_ * NK_) / 128), 256>>>(xr, kv_w, nullptr, kv,
                                                              B_ * NK_, 2 * C_, C_);
    // fused attention
    attn_kernel<<<dim3(N_ / 64, 8, B_), 256, ATTN_SMEM>>>(q, kv, ao);

    // output projection (+proj_b) into d_out
    hgemm<0><<<dim3(C_ / 128, (B_ * N_) / 128), 256>>>(ao, proj_w, proj_b, out,
                                                       B_ * N_, C_, C_);
}

// round 8
// speedup vs baseline: 2.0745x; 1.5960x over previous
#include <cuda_runtime.h>
#include <cuda_bf16.h>
#include <cstdint>

#define B_   4
#define N_   4096
#define C_   512
#define NK_  1024
#define KCONV 2048

// ---------------- scratch ----------------
__device__ float g_q  [B_ * N_  * C_];
__device__ float g_xr [B_ * NK_ * C_];
__device__ float g_kv [B_ * NK_ * 2 * C_];
__device__ float g_ao [B_ * N_  * C_];
__device__ float g_wsr [C_ * KCONV];   // sr_w reordered: [n][k'], k' = ij*512 + ci

// ---------------- mma / split helpers ----------------
__device__ __forceinline__ void mma16816(float* c, const uint32_t* a, const uint32_t* b){
    asm volatile("mma.sync.aligned.m16n8k16.row.col.f32.bf16.bf16.f32 "
        "{%0,%1,%2,%3}, {%4,%5,%6,%7}, {%8,%9}, {%0,%1,%2,%3};"
        : "+f"(c[0]), "+f"(c[1]), "+f"(c[2]), "+f"(c[3])
        : "r"(a[0]), "r"(a[1]), "r"(a[2]), "r"(a[3]), "r"(b[0]), "r"(b[1]));
}
__device__ __forceinline__ void split2(float x, float y, uint32_t& h, uint32_t& l){
    __nv_bfloat162 hh = __float22bfloat162_rn(make_float2(x, y));
    float2 hf = __bfloat1622float2(hh);
    __nv_bfloat162 ll = __float22bfloat162_rn(make_float2(x - hf.x, y - hf.y));
    h = *(uint32_t*)&hh; l = *(uint32_t*)&ll;
}

// sr_w[n][ci][i][j] -> wsr[n][k'], k' = ij*512 + ci
__global__ void reorder_sr(const float* __restrict__ w, float* __restrict__ wt) {
    int idx = blockIdx.x * 256 + threadIdx.x;
    int n = idx >> 11, k = idx & 2047;
    int ij = k >> 9, ci = k & 511;
    wt[idx] = w[((size_t)n * C_ + ci) * 4 + ij];
}

// ---------------- tensor-core GEMM (unchanged from passing R6) ----------------
template <int MODE>
__global__ __launch_bounds__(256)
void hgemm(const float* __restrict__ A, const float* __restrict__ Bw,
           const float* __restrict__ bias, float* __restrict__ out,
           int M, int N, int K) {
    __shared__ uint32_t sAh[128 * 20], sAl[128 * 20];
    __shared__ uint32_t sBh[128 * 20], sBl[128 * 20];

    const int tid  = threadIdx.x;
    const int lane = tid & 31, warp = tid >> 5;
    const int wm = (warp >> 2) * 64, wn = (warp & 3) * 32;
    const int bx = blockIdx.x * 128, by = blockIdx.y * 128;

    float acc[4][4][4];
#pragma unroll
    for (int i = 0; i < 4; i++)
#pragma unroll
        for (int j = 0; j < 4; j++)
#pragma unroll
            for (int r = 0; r < 4; r++) acc[i][j][r] = 0.f;

    const int lrow = tid >> 1;
    const int lkq  = (tid & 1) * 16;

    for (int kc = 0; kc < K; kc += 32) {
#pragma unroll
        for (int f = 0; f < 4; f++) {
            int k = lkq + 4 * f;
            size_t aoff;
            if (MODE == 0) {
                aoff = (size_t)(by + lrow) * K + kc + k;
            } else {
                int m = by + lrow;
                int bb = m >> 10, pp = m & 1023, ph = pp >> 5, pw = pp & 31;
                int kg = kc + k;
                int ij = kg >> 9, ci = kg & 511;
                int pix = (2 * ph + (ij >> 1)) * 64 + 2 * pw + (ij & 1);
                aoff = ((size_t)(bb << 12) + pix) * C_ + ci;
            }
            float4 va = *reinterpret_cast<const float4*>(A + aoff);
            float4 vb = *reinterpret_cast<const float4*>(
                            Bw + (size_t)(bx + lrow) * K + kc + k);
            int u = lrow * 20 + (k >> 1);
            split2(va.x, va.y, sAh[u],     sAl[u]);
            split2(va.z, va.w, sAh[u + 1], sAl[u + 1]);
            split2(vb.x, vb.y, sBh[u],     sBl[u]);
            split2(vb.z, vb.w, sBh[u + 1], sBl[u + 1]);
        }
        __syncthreads();

#pragma unroll
        for (int kh = 0; kh < 2; kh++) {
            uint32_t ah[4][4], al[4][4], bh[4][2], bl[4][2];
            const int cq = kh * 8 + (lane & 3);
            const int rq = lane >> 2;
#pragma unroll
            for (int mt = 0; mt < 4; mt++) {
                int r0 = (wm + 16 * mt + rq) * 20;
                int r1 = r0 + 8 * 20;
                ah[mt][0] = sAh[r0 + cq];     ah[mt][1] = sAh[r1 + cq];
                ah[mt][2] = sAh[r0 + cq + 4]; ah[mt][3] = sAh[r1 + cq + 4];
                al[mt][0] = sAl[r0 + cq];     al[mt][1] = sAl[r1 + cq];
                al[mt][2] = sAl[r0 + cq + 4]; al[mt][3] = sAl[r1 + cq + 4];
            }
#pragma unroll
            for (int nt = 0; nt < 4; nt++) {
                int rb = (wn + 8 * nt + rq) * 20;
                bh[nt][0] = sBh[rb + cq]; bh[nt][1] = sBh[rb + cq + 4];
                bl[nt][0] = sBl[rb + cq]; bl[nt][1] = sBl[rb + cq + 4];
            }
#pragma unroll
            for (int mt = 0; mt < 4; mt++)
#pragma unroll
                for (int nt = 0; nt < 4; nt++) {
                    mma16816(acc[mt][nt], ah[mt], bh[nt]);
                    mma16816(acc[mt][nt], ah[mt], bl[nt]);
                    mma16816(acc[mt][nt], al[mt], bh[nt]);
                }
        }
        __syncthreads();
    }

    const int rq = lane >> 2, cq = 2 * (lane & 3);
#pragma unroll
    for (int mt = 0; mt < 4; mt++) {
#pragma unroll
        for (int nt = 0; nt < 4; nt++) {
            int col = bx + wn + 8 * nt + cq;
            float bx0 = bias ? bias[col] : 0.f;
            float bx1 = bias ? bias[col + 1] : 0.f;
            int r0 = by + wm + 16 * mt + rq;
            float2 v0 = make_float2(acc[mt][nt][0] + bx0, acc[mt][nt][1] + bx1);
            float2 v1 = make_float2(acc[mt][nt][2] + bx0, acc[mt][nt][3] + bx1);
            *reinterpret_cast<float2*>(out + (size_t)r0 * N + col) = v0;
            *reinterpret_cast<float2*>(out + (size_t)(r0 + 8) * N + col) = v1;
        }
    }
}

// ---------------- tensor-core flash attention ----------------
// Block: 128 queries x one (b,h); 8 warps, 16 queries/warp; K/V tiles of 64.
// SMEM (u32 units, row stride 36): Qh[128][36] Ql[128][36] Kh[64][36] Kl Vth Vtl.
// V is stored TRANSPOSED: Vt[d][key-pair u32].
#define AT_U32  (2*128*36 + 4*64*36)
#define AT_SMEM (AT_U32 * 4)

__global__ __launch_bounds__(256)
void attn_mma(const float* __restrict__ Q, const float* __restrict__ KV,
              float* __restrict__ O) {
    extern __shared__ uint32_t su[];
    uint32_t* sQh = su;
    uint32_t* sQl = su + 128 * 36;
    uint32_t* sKh = su + 2 * 128 * 36;
    uint32_t* sKl = sKh + 64 * 36;
    uint32_t* sVh = sKl + 64 * 36;
    uint32_t* sVl = sVh + 64 * 36;

    const int tid  = threadIdx.x;
    const int lane = tid & 31, warp = tid >> 5;
    const int rq = lane >> 2, tq = lane & 3;
    const int qb = blockIdx.x * 128;
    const int h  = blockIdx.y;
    const int b  = blockIdx.z;

    // ---- load Q tile [128 q][64 d] -> bf16 h/l ----
    {
        const float* qg = Q + ((size_t)(b * N_ + qb)) * C_ + h * 64;
        int row = tid >> 1, cb = (tid & 1) * 32;
#pragma unroll
        for (int f = 0; f < 8; f++) {
            float4 v = *reinterpret_cast<const float4*>(qg + (size_t)row * C_ + cb + 4 * f);
            int u = row * 36 + (cb >> 1) + 2 * f;
            split2(v.x, v.y, sQh[u],     sQl[u]);
            split2(v.z, v.w, sQh[u + 1], sQl[u + 1]);
        }
    }
    __syncthreads();

    // ---- Q fragments (held in registers for whole kernel) ----
    uint32_t qah[4][4], qal[4][4];
    {
        int base = (warp * 16 + rq) * 36 + tq;
#pragma unroll
        for (int kc = 0; kc < 4; kc++) {
            int r0 = base + 8 * kc;
            qah[kc][0] = sQh[r0];          qah[kc][1] = sQh[r0 + 288];
            qah[kc][2] = sQh[r0 + 4];      qah[kc][3] = sQh[r0 + 292];
            qal[kc][0] = sQl[r0];          qal[kc][1] = sQl[r0 + 288];
            qal[kc][2] = sQl[r0 + 4];      qal[kc][3] = sQl[r0 + 292];
        }
    }

    float oacc[8][4];
#pragma unroll
    for (int nt = 0; nt < 8; nt++)
#pragma unroll
        for (int r = 0; r < 4; r++) oacc[nt][r] = 0.f;
    float m0 = -1e30f, m1 = -1e30f, l0 = 0.f, l1 = 0.f;

    const float* kvg = KV + (size_t)b * NK_ * (2 * C_) + h * 64;

    for (int t = 0; t < NK_ / 64; t++) {
        __syncthreads();
        // ---- load K tile [64 key][64 d] ----
        {
            int row = tid >> 2, cb = (tid & 3) * 16;
            const float* kg = kvg + (size_t)(t * 64 + row) * (2 * C_);
#pragma unroll
            for (int f = 0; f < 4; f++) {
                float4 v = *reinterpret_cast<const float4*>(kg + cb + 4 * f);
                int u = row * 36 + (cb >> 1) + 2 * f;
                split2(v.x, v.y, sKh[u],     sKl[u]);
                split2(v.z, v.w, sKh[u + 1], sKl[u + 1]);
            }
        }
        // ---- load V tile transposed: Vt[d][key-pair] ----
        {
            int p = tid >> 3, dl = tid & 7;           // key pair, d low bits
            const float* vg = kvg + C_ + (size_t)(t * 64 + 2 * p) * (2 * C_);
#pragma unroll
            for (int i = 0; i < 8; i++) {
                int d = dl + 8 * i;
                float v0 = vg[d];
                float v1 = vg[2 * C_ + d];
                split2(v0, v1, sVh[d * 36 + p], sVl[d * 36 + p]);
            }
        }
        __syncthreads();

        // ---- S = Q K^T (16q x 64key per warp) ----
        float sacc[8][4];
#pragma unroll
        for (int nt = 0; nt < 8; nt++)
#pragma unroll
            for (int r = 0; r < 4; r++) sacc[nt][r] = 0.f;
#pragma unroll
        for (int nt = 0; nt < 8; nt++) {
            int rb = (8 * nt + rq) * 36 + tq;
#pragma unroll
            for (int kc = 0; kc < 4; kc++) {
                uint32_t bh[2], bl[2];
                bh[0] = sKh[rb + 8 * kc]; bh[1] = sKh[rb + 8 * kc + 4];
                bl[0] = sKl[rb + 8 * kc]; bl[1] = sKl[rb + 8 * kc + 4];
                mma16816(sacc[nt], qah[kc], bh);
                mma16816(sacc[nt], qah[kc], bl);
                mma16816(sacc[nt], qal[kc], bh);
            }
        }

        // ---- online softmax (rows rq and rq+8; row lives in 4 lanes) ----
        float tm0 = -1e30f, tm1 = -1e30f;
#pragma unroll
        for (int nt = 0; nt < 8; nt++) {
            tm0 = fmaxf(tm0, fmaxf(sacc[nt][0], sacc[nt][1]));
            tm1 = fmaxf(tm1, fmaxf(sacc[nt][2], sacc[nt][3]));
        }
#pragma unroll
        for (int o = 1; o <= 2; o <<= 1) {
            tm0 = fmaxf(tm0, __shfl_xor_sync(0xffffffffu, tm0, o));
            tm1 = fmaxf(tm1, __shfl_xor_sync(0xffffffffu, tm1, o));
        }
        float mn0 = fmaxf(m0, tm0), mn1 = fmaxf(m1, tm1);
        float al0 = __expf(0.125f * (m0 - mn0));
        float al1 = __expf(0.125f * (m1 - mn1));
        float rs0 = 0.f, rs1 = 0.f;
#pragma unroll
        for (int nt = 0; nt < 8; nt++) {
            float p0 = __expf(0.125f * (sacc[nt][0] - mn0));
            float p1 = __expf(0.125f * (sacc[nt][1] - mn0));
            float p2 = __expf(0.125f * (sacc[nt][2] - mn1));
            float p3 = __expf(0.125f * (sacc[nt][3] - mn1));
            sacc[nt][0] = p0; sacc[nt][1] = p1; sacc[nt][2] = p2; sacc[nt][3] = p3;
            rs0 += p0 + p1; rs1 += p2 + p3;
        }
#pragma unroll
        for (int o = 1; o <= 2; o <<= 1) {
            rs0 += __shfl_xor_sync(0xffffffffu, rs0, o);
            rs1 += __shfl_xor_sync(0xffffffffu, rs1, o);
        }
        l0 = l0 * al0 + rs0;  l1 = l1 * al1 + rs1;
        m0 = mn0;             m1 = mn1;
#pragma unroll
        for (int nt = 0; nt < 8; nt++) {
            oacc[nt][0] *= al0; oacc[nt][1] *= al0;
            oacc[nt][2] *= al1; oacc[nt][3] *= al1;
        }

        // ---- P (C-frag) -> A-frags, in registers ----
        uint32_t pah[4][4], pal[4][4];
#pragma unroll
        for (int kc = 0; kc < 4; kc++) {
            split2(sacc[2*kc][0],   sacc[2*kc][1],   pah[kc][0], pal[kc][0]);
            split2(sacc[2*kc][2],   sacc[2*kc][3],   pah[kc][1], pal[kc][1]);
            split2(sacc[2*kc+1][0], sacc[2*kc+1][1], pah[kc][2], pal[kc][2]);
            split2(sacc[2*kc+1][2], sacc[2*kc+1][3], pah[kc][3], pal[kc][3]);
        }

        // ---- O += P V ----
#pragma unroll
        for (int nt = 0; nt < 8; nt++) {
            int vb = (8 * nt + rq) * 36 + tq;
#pragma unroll
            for (int kc = 0; kc < 4; kc++) {
                uint32_t bh[2], bl[2];
                bh[0] = sVh[vb + 8 * kc]; bh[1] = sVh[vb + 8 * kc + 4];
                bl[0] = sVl[vb + 8 * kc]; bl[1] = sVl[vb + 8 * kc + 4];
                mma16816(oacc[nt], pah[kc], bh);
                mma16816(oacc[nt], pal[kc], bh);
                mma16816(oacc[nt], pah[kc], bl);
            }
        }
    }

    // ---- epilogue ----
    float inv0 = 1.f / l0, inv1 = 1.f / l1;
    int row0 = qb + warp * 16 + rq;
    float* og = O + (size_t)(b * N_) * C_ + h * 64;
#pragma unroll
    for (int nt = 0; nt < 8; nt++) {
        int d = 8 * nt + 2 * tq;
        *reinterpret_cast<float2*>(og + (size_t)row0 * C_ + d) =
            make_float2(oacc[nt][0] * inv0, oacc[nt][1] * inv0);
        *reinterpret_cast<float2*>(og + (size_t)(row0 + 8) * C_ + d) =
            make_float2(oacc[nt][2] * inv1, oacc[nt][3] * inv1);
    }
}

// ---------------- launch ----------------
extern "C" void kernel_launch(void* const* d_in, const int* in_sizes, int n_in,
                              void* d_out, int out_size) {
    const float* x      = (const float*)d_in[0];
    const float* q_w    = (const float*)d_in[1];
    const float* kv_w   = (const float*)d_in[2];
    const float* sr_w   = (const float*)d_in[3];
    const float* sr_b   = (const float*)d_in[4];
    const float* proj_w = (const float*)d_in[5];
    const float* proj_b = (const float*)d_in[6];
    float* out = (float*)d_out;

    float *q, *xr, *kv, *ao, *wsr;
    cudaGetSymbolAddress((void**)&q,   g_q);
    cudaGetSymbolAddress((void**)&xr,  g_xr);
    cudaGetSymbolAddress((void**)&kv,  g_kv);
    cudaGetSymbolAddress((void**)&ao,  g_ao);
    cudaGetSymbolAddress((void**)&wsr, g_wsr);

    cudaFuncSetAttribute(attn_mma, cudaFuncAttributeMaxDynamicSharedMemorySize, AT_SMEM);

    reorder_sr<<<(C_ * KCONV) / 256, 256>>>(sr_w, wsr);

    hgemm<0><<<dim3(C_ / 128, (B_ * N_) / 128), 256>>>(x, q_w, nullptr, q,
                                                       B_ * N_, C_, C_);
    hgemm<1><<<dim3(C_ / 128, (B_ * NK_) / 128), 256>>>(x, wsr, sr_b, xr,
                                                        B_ * NK_, C_, KCONV);
    hgemm<0><<<dim3((2 * C_) / 128, (B_ * NK_) / 128), 256>>>(xr, kv_w, nullptr, kv,
                                                              B_ * NK_, 2 * C_, C_);
    attn_mma<<<dim3(N_ / 128, 8, B_), 256, AT_SMEM>>>(q, kv, ao);
    hgemm<0><<<dim3(C_ / 128, (B_ * N_) / 128), 256>>>(ao, proj_w, proj_b, out,
                                                       B_ * N_, C_, C_);
}

// round 11
// speedup vs baseline: 2.4819x; 1.1964x over previous
#include <cuda_runtime.h>
#include <cuda_bf16.h>
#include <cstdint>

#define B_   4
#define N_   4096
#define C_   512
#define NK_  1024
#define KCONV 2048
typedef __nv_bfloat16 bf16;

// ---------------- scratch ----------------
__device__ bf16 g_xh [B_*N_*C_],  g_xl [B_*N_*C_];     // x split
__device__ bf16 g_qh [B_*N_*C_],  g_ql [B_*N_*C_];     // q proj
__device__ bf16 g_xrh[B_*NK_*C_], g_xrl[B_*NK_*C_];    // reduced x
__device__ bf16 g_kvh[B_*NK_*2*C_], g_kvl[B_*NK_*2*C_];
__device__ bf16 g_aoh[B_*N_*C_],  g_aol[B_*N_*C_];     // attn out
__device__ bf16 g_qwh [C_*C_],    g_qwl [C_*C_];
__device__ bf16 g_kvwh[2*C_*C_],  g_kvwl[2*C_*C_];
__device__ bf16 g_srh [C_*KCONV], g_srl [C_*KCONV];
__device__ bf16 g_prh [C_*C_],    g_prl [C_*C_];

// ---------------- helpers ----------------
__device__ __forceinline__ uint32_t s2u(const void* p){
    uint32_t a;
    asm("{ .reg .u64 t; cvta.to.shared.u64 t, %1; cvt.u32.u64 %0, t; }" : "=r"(a) : "l"(p));
    return a;
}
__device__ __forceinline__ void mma16816(float* c, const uint32_t* a, const uint32_t* b){
    asm volatile("mma.sync.aligned.m16n8k16.row.col.f32.bf16.bf16.f32 "
        "{%0,%1,%2,%3}, {%4,%5,%6,%7}, {%8,%9}, {%0,%1,%2,%3};"
        : "+f"(c[0]), "+f"(c[1]), "+f"(c[2]), "+f"(c[3])
        : "r"(a[0]), "r"(a[1]), "r"(a[2]), "r"(a[3]), "r"(b[0]), "r"(b[1]));
}
__device__ __forceinline__ void split2(float x, float y, uint32_t& h, uint32_t& l){
    __nv_bfloat162 hh = __float22bfloat162_rn(make_float2(x, y));
    float2 hf = __bfloat1622float2(hh);
    __nv_bfloat162 ll = __float22bfloat162_rn(make_float2(x - hf.x, y - hf.y));
    h = *(uint32_t*)&hh; l = *(uint32_t*)&ll;
}
__device__ __forceinline__ void ldmx4(uint32_t* r, uint32_t a){
    asm volatile("ldmatrix.sync.aligned.m8n8.x4.shared.b16 {%0,%1,%2,%3}, [%4];"
        : "=r"(r[0]), "=r"(r[1]), "=r"(r[2]), "=r"(r[3]) : "r"(a));
}
__device__ __forceinline__ void ldmx4t(uint32_t* r, uint32_t a){
    asm volatile("ldmatrix.sync.aligned.m8n8.x4.trans.shared.b16 {%0,%1,%2,%3}, [%4];"
        : "=r"(r[0]), "=r"(r[1]), "=r"(r[2]), "=r"(r[3]) : "r"(a));
}
__device__ __forceinline__ void cpa(uint32_t s, const void* g){
    asm volatile("cp.async.cg.shared.global [%0], [%1], 16;" :: "r"(s), "l"(g));
}
#define CP_COMMIT() asm volatile("cp.async.commit_group;" ::: "memory")

// ---------------- prep: fp32 -> bf16 hi/lo ----------------
__global__ void f2hl(const float* __restrict__ s, bf16* __restrict__ h,
                     bf16* __restrict__ l, int n){
    int i = (blockIdx.x * 256 + threadIdx.x) * 4;
    if (i >= n) return;
    float4 v = *reinterpret_cast<const float4*>(s + i);
    uint32_t h0, l0, h1, l1;
    split2(v.x, v.y, h0, l0);
    split2(v.z, v.w, h1, l1);
    *reinterpret_cast<uint2*>(h + i) = make_uint2(h0, h1);
    *reinterpret_cast<uint2*>(l + i) = make_uint2(l0, l1);
}
// sr_w[n][ci][i][j] -> [n][k'=ij*512+ci] split
__global__ void srhl(const float* __restrict__ w, bf16* __restrict__ h,
                     bf16* __restrict__ l){
    int idx = blockIdx.x * 256 + threadIdx.x;    // over 512*2048
    int n = idx >> 11, k = idx & 2047;
    int ij = k >> 9, ci = k & 511;
    float v = w[((size_t)n * C_ + ci) * 4 + ij];
    bf16 hh = __float2bfloat16(v);
    h[idx] = hh;
    l[idx] = __float2bfloat16(v - __bfloat162float(hh));
}

// ---------------- bf16 hi/lo tensor GEMM: out = A @ B^T (+bias) ----------------
// 128x128 block, 8 warps (64x32 warp tiles), KT=32, cp.async double-buffer.
// SMEM per stage: Ah,Al,Bh,Bl each [128 rows][20 u32] (stride 80B, ldmatrix-conflict-free).
#define HG_STG   40960
#define HG_SMEM  (2 * HG_STG)

template <int MODE>
__global__ __launch_bounds__(256)
void hgemm(const bf16* __restrict__ Ah_, const bf16* __restrict__ Al_,
           const bf16* __restrict__ Bh_, const bf16* __restrict__ Bl_,
           const float* __restrict__ bias, float* __restrict__ outF,
           bf16* __restrict__ outH, bf16* __restrict__ outL,
           int M, int N, int K) {
    extern __shared__ char smc[];
    const uint32_t sb = s2u(smc);
    const int tid  = threadIdx.x;
    const int lane = tid & 31, warp = tid >> 5;
    const int wm = (warp >> 2) * 64, wn = (warp & 3) * 32;
    const int bx = blockIdx.x * 128, by = blockIdx.y * 128;

    float acc[4][4][4];
#pragma unroll
    for (int i = 0; i < 4; i++)
#pragma unroll
        for (int j = 0; j < 4; j++)
#pragma unroll
            for (int r = 0; r < 4; r++) acc[i][j][r] = 0.f;

    const int NC = K >> 5;

    auto stage_load = [&](int kci, int st){
        int k0 = kci << 5;
#pragma unroll
        for (int p = 0; p < 2; p++) {
            int id = tid + p * 256;
            int row = id >> 2, ch = id & 3;
            int kg = k0 + ch * 8;
            size_t aoff;
            if (MODE == 0) {
                aoff = (size_t)(by + row) * K + kg;
            } else {
                int m = by + row;
                int bb = m >> 10, pp = m & 1023, ph = pp >> 5, pw = pp & 31;
                int ij = kg >> 9, ci = kg & 511;
                int pix = (2 * ph + (ij >> 1)) * 64 + 2 * pw + (ij & 1);
                aoff = ((size_t)(bb << 12) + pix) * C_ + ci;
            }
            size_t boff = (size_t)(bx + row) * K + kg;
            uint32_t si = sb + st * HG_STG + row * 80 + ch * 16;
            cpa(si,         Ah_ + aoff);
            cpa(si + 10240, Al_ + aoff);
            cpa(si + 20480, Bh_ + boff);
            cpa(si + 30720, Bl_ + boff);
        }
        CP_COMMIT();
    };

    const int lm = lane >> 3, lr = lane & 7;
    const int aro = (lm & 1) * 8, aco = (lm >> 1) * 4;   // A frag pattern
    const int bro = (lm >> 1) * 8, bco = (lm & 1) * 4;   // B frag pattern

    stage_load(0, 0);

    for (int i = 0; i < NC; i++) {
        int st = i & 1;
        if (i + 1 < NC) stage_load(i + 1, st ^ 1);
        if (i + 1 < NC) asm volatile("cp.async.wait_group 1;" ::: "memory");
        else            asm volatile("cp.async.wait_group 0;" ::: "memory");
        __syncthreads();

        const uint32_t sA = sb + st * HG_STG;
#pragma unroll
        for (int kh = 0; kh < 2; kh++) {
            uint32_t ah[4][4], al[4][4], bh[2][4], bl[2][4];
#pragma unroll
            for (int mt = 0; mt < 4; mt++) {
                uint32_t ad = sA + ((wm + 16 * mt + aro + lr) * 20 + kh * 8 + aco) * 4;
                ldmx4(ah[mt], ad);
                ldmx4(al[mt], ad + 10240);
            }
#pragma unroll
            for (int ntp = 0; ntp < 2; ntp++) {
                uint32_t bd = sA + 20480 + ((wn + 16 * ntp + bro + lr) * 20 + kh * 8 + bco) * 4;
                ldmx4(bh[ntp], bd);
                ldmx4(bl[ntp], bd + 10240);
            }
#pragma unroll
            for (int mt = 0; mt < 4; mt++)
#pragma unroll
                for (int nt = 0; nt < 4; nt++) {
                    const uint32_t* ph = &bh[nt >> 1][(nt & 1) * 2];
                    const uint32_t* pl = &bl[nt >> 1][(nt & 1) * 2];
                    mma16816(acc[mt][nt], ah[mt], ph);
                    mma16816(acc[mt][nt], ah[mt], pl);
                    mma16816(acc[mt][nt], al[mt], ph);
                }
        }
        __syncthreads();
    }

    // epilogue: direct global writes (fp32 and/or bf16 h/l)
    const int rq = lane >> 2, cq = 2 * (lane & 3);
#pragma unroll
    for (int mt = 0; mt < 4; mt++) {
#pragma unroll
        for (int nt = 0; nt < 4; nt++) {
            int col = bx + wn + 8 * nt + cq;
            float b0 = bias ? bias[col] : 0.f;
            float b1 = bias ? bias[col + 1] : 0.f;
            int r0 = by + wm + 16 * mt + rq;
            float v00 = acc[mt][nt][0] + b0, v01 = acc[mt][nt][1] + b1;
            float v10 = acc[mt][nt][2] + b0, v11 = acc[mt][nt][3] + b1;
            if (outF) {
                *reinterpret_cast<float2*>(outF + (size_t)r0 * N + col) = make_float2(v00, v01);
                *reinterpret_cast<float2*>(outF + (size_t)(r0 + 8) * N + col) = make_float2(v10, v11);
            }
            if (outH) {
                uint32_t h, l;
                split2(v00, v01, h, l);
                *reinterpret_cast<uint32_t*>(outH + (size_t)r0 * N + col) = h;
                *reinterpret_cast<uint32_t*>(outL + (size_t)r0 * N + col) = l;
                split2(v10, v11, h, l);
                *reinterpret_cast<uint32_t*>(outH + (size_t)(r0 + 8) * N + col) = h;
                *reinterpret_cast<uint32_t*>(outL + (size_t)(r0 + 8) * N + col) = l;
            }
        }
    }
}

// ---------------- tensor-core flash attention (bf16 h/l inputs) ----------------
// 128 queries x (b,h) per block; 8 warps x 16 q; K/V tiles of 64 keys.
// SMEM u32 stride 36 (144B rows): Qh[128] Ql[128] Kh[64] Kl[64] Vh[64] Vl[64].
#define AT_SMEM ((2*128 + 4*64) * 36 * 4)

__global__ __launch_bounds__(256)
void attn_mma(const bf16* __restrict__ Qh_, const bf16* __restrict__ Ql_,
              const bf16* __restrict__ KVh_, const bf16* __restrict__ KVl_,
              bf16* __restrict__ Oh, bf16* __restrict__ Ol) {
    extern __shared__ uint32_t su[];
    uint32_t* sQh = su;
    uint32_t* sQl = su + 128 * 36;
    uint32_t* sKh = su + 2 * 128 * 36;
    uint32_t* sKl = sKh + 64 * 36;
    uint32_t* sVh = sKl + 64 * 36;
    uint32_t* sVl = sVh + 64 * 36;
    const uint32_t uQh = s2u(sQh), uKh = s2u(sKh), uVh = s2u(sVh);

    const int tid  = threadIdx.x;
    const int lane = tid & 31, warp = tid >> 5;
    const int rq = lane >> 2, tq = lane & 3;
    const int qb = blockIdx.x * 128;
    const int h  = blockIdx.y;
    const int b  = blockIdx.z;

    const int lm = lane >> 3, lr = lane & 7;
    const int aro = (lm & 1) * 8, aco = (lm >> 1) * 4;   // A pattern
    const int bro = (lm >> 1) * 8, bco = (lm & 1) * 4;   // B pattern
    const int vro = (lm & 1) * 8, vns = (lm >> 1);       // V-trans pattern

    // ---- load Q tile [128 q][64 d] bf16 h/l  (2048 16B-chunks total) ----
    {
        size_t qo = ((size_t)(b * N_ + qb)) * C_ + h * 64;
#pragma unroll
        for (int p = 0; p < 8; p++) {
            int id = tid + p * 256;                 // 0..2047
            int arr = id >> 10, rem = id & 1023;    // 1024 chunks per array
            int row = rem >> 3, ch = rem & 7;
            const bf16* src = (arr ? Ql_ : Qh_) + qo + (size_t)row * C_ + ch * 8;
            uint32_t* dst = (arr ? sQl : sQh) + row * 36 + ch * 4;
            *reinterpret_cast<uint4*>(dst) = *reinterpret_cast<const uint4*>(src);
        }
    }
    __syncthreads();

    // ---- Q fragments in registers ----
    uint32_t qah[4][4], qal[4][4];
#pragma unroll
    for (int kc = 0; kc < 4; kc++) {
        uint32_t ad = uQh + ((warp * 16 + aro + lr) * 36 + kc * 8 + aco) * 4;
        ldmx4(qah[kc], ad);
        ldmx4(qal[kc], ad + 128 * 36 * 4);
    }

    float oacc[8][4];
#pragma unroll
    for (int nt = 0; nt < 8; nt++)
#pragma unroll
        for (int r = 0; r < 4; r++) oacc[nt][r] = 0.f;
    float m0 = -1e30f, m1 = -1e30f, l0 = 0.f, l1 = 0.f;

    const size_t kvo = (size_t)b * NK_ * (2 * C_) + h * 64;

    for (int t = 0; t < NK_ / 64; t++) {
        __syncthreads();
        // ---- load K,V tiles [64 keys][64 d] h/l (4 arrays x 512 chunks) ----
#pragma unroll
        for (int p = 0; p < 8; p++) {
            int id = tid + p * 256;                 // 0..2047
            int arr = id >> 9, rem = id & 511;
            int row = rem >> 3, ch = rem & 7;
            const bf16* base = (arr & 1) ? KVl_ : KVh_;
            size_t off = kvo + (size_t)(t * 64 + row) * (2 * C_) + ((arr >> 1) ? C_ : 0) + ch * 8;
            uint32_t* dst = (arr == 0 ? sKh : arr == 1 ? sKl : arr == 2 ? sVh : sVl)
                            + row * 36 + ch * 4;
            *reinterpret_cast<uint4*>(dst) = *reinterpret_cast<const uint4*>(base + off);
        }
        __syncthreads();

        // ---- S = Q K^T ----
        float sacc[8][4];
#pragma unroll
        for (int nt = 0; nt < 8; nt++)
#pragma unroll
            for (int r = 0; r < 4; r++) sacc[nt][r] = 0.f;
#pragma unroll
        for (int kc = 0; kc < 4; kc++) {
#pragma unroll
            for (int ntp = 0; ntp < 4; ntp++) {
                uint32_t bh4[4], bl4[4];
                uint32_t bd = uKh + ((16 * ntp + bro + lr) * 36 + kc * 8 + bco) * 4;
                ldmx4(bh4, bd);
                ldmx4(bl4, bd + 64 * 36 * 4);
#pragma unroll
                for (int s = 0; s < 2; s++) {
                    mma16816(sacc[2 * ntp + s], qah[kc], &bh4[s * 2]);
                    mma16816(sacc[2 * ntp + s], qah[kc], &bl4[s * 2]);
                    mma16816(sacc[2 * ntp + s], qal[kc], &bh4[s * 2]);
                }
            }
        }

        // ---- online softmax ----
        float tm0 = -1e30f, tm1 = -1e30f;
#pragma unroll
        for (int nt = 0; nt < 8; nt++) {
            tm0 = fmaxf(tm0, fmaxf(sacc[nt][0], sacc[nt][1]));
            tm1 = fmaxf(tm1, fmaxf(sacc[nt][2], sacc[nt][3]));
        }
#pragma unroll
        for (int o = 1; o <= 2; o <<= 1) {
            tm0 = fmaxf(tm0, __shfl_xor_sync(0xffffffffu, tm0, o));
            tm1 = fmaxf(tm1, __shfl_xor_sync(0xffffffffu, tm1, o));
        }
        float mn0 = fmaxf(m0, tm0), mn1 = fmaxf(m1, tm1);
        float al0 = __expf(0.125f * (m0 - mn0));
        float al1 = __expf(0.125f * (m1 - mn1));
        float rs0 = 0.f, rs1 = 0.f;
#pragma unroll
        for (int nt = 0; nt < 8; nt++) {
            float p0 = __expf(0.125f * (sacc[nt][0] - mn0));
            float p1 = __expf(0.125f * (sacc[nt][1] - mn0));
            float p2 = __expf(0.125f * (sacc[nt][2] - mn1));
            float p3 = __expf(0.125f * (sacc[nt][3] - mn1));
            sacc[nt][0] = p0; sacc[nt][1] = p1; sacc[nt][2] = p2; sacc[nt][3] = p3;
            rs0 += p0 + p1; rs1 += p2 + p3;
        }
#pragma unroll
        for (int o = 1; o <= 2; o <<= 1) {
            rs0 += __shfl_xor_sync(0xffffffffu, rs0, o);
            rs1 += __shfl_xor_sync(0xffffffffu, rs1, o);
        }
        l0 = l0 * al0 + rs0;  l1 = l1 * al1 + rs1;
        m0 = mn0;             m1 = mn1;
#pragma unroll
        for (int nt = 0; nt < 8; nt++) {
            oacc[nt][0] *= al0; oacc[nt][1] *= al0;
            oacc[nt][2] *= al1; oacc[nt][3] *= al1;
        }

        // ---- P -> A-frags (registers only) ----
        uint32_t pah[4][4], pal[4][4];
#pragma unroll
        for (int kc = 0; kc < 4; kc++) {
            split2(sacc[2*kc][0],   sacc[2*kc][1],   pah[kc][0], pal[kc][0]);
            split2(sacc[2*kc][2],   sacc[2*kc][3],   pah[kc][1], pal[kc][1]);
            split2(sacc[2*kc+1][0], sacc[2*kc+1][1], pah[kc][2], pal[kc][2]);
            split2(sacc[2*kc+1][2], sacc[2*kc+1][3], pah[kc][3], pal[kc][3]);
        }

        // ---- O += P V  (V^T frags via ldmatrix.trans) ----
#pragma unroll
        for (int kc = 0; kc < 4; kc++) {
#pragma unroll
            for (int ntp = 0; ntp < 4; ntp++) {
                uint32_t vh4[4], vl4[4];
                uint32_t vd = uVh + ((16 * kc + vro + lr) * 36 + (2 * ntp + vns) * 4) * 4;
                ldmx4t(vh4, vd);
                ldmx4t(vl4, vd + 64 * 36 * 4);
#pragma unroll
                for (int s = 0; s < 2; s++) {
                    mma16816(oacc[2 * ntp + s], pah[kc], &vh4[s * 2]);
                    mma16816(oacc[2 * ntp + s], pal[kc], &vh4[s * 2]);
                    mma16816(oacc[2 * ntp + s], pah[kc], &vl4[s * 2]);
                }
            }
        }
    }

    // ---- epilogue -> bf16 h/l ----
    float inv0 = 1.f / l0, inv1 = 1.f / l1;
    int row0 = qb + warp * 16 + rq;
    size_t ob = (size_t)(b * N_) * C_ + h * 64;
#pragma unroll
    for (int nt = 0; nt < 8; nt++) {
        int d = 8 * nt + 2 * tq;
        uint32_t hh, ll;
        split2(oacc[nt][0] * inv0, oacc[nt][1] * inv0, hh, ll);
        *reinterpret_cast<uint32_t*>(Oh + ob + (size_t)row0 * C_ + d) = hh;
        *reinterpret_cast<uint32_t*>(Ol + ob + (size_t)row0 * C_ + d) = ll;
        split2(oacc[nt][2] * inv1, oacc[nt][3] * inv1, hh, ll);
        *reinterpret_cast<uint32_t*>(Oh + ob + (size_t)(row0 + 8) * C_ + d) = hh;
        *reinterpret_cast<uint32_t*>(Ol + ob + (size_t)(row0 + 8) * C_ + d) = ll;
    }
}

// ---------------- launch ----------------
extern "C" void kernel_launch(void* const* d_in, const int* in_sizes, int n_in,
                              void* d_out, int out_size) {
    const float* x      = (const float*)d_in[0];
    const float* q_w    = (const float*)d_in[1];
    const float* kv_w   = (const float*)d_in[2];
    const float* sr_w   = (const float*)d_in[3];
    const float* sr_b   = (const float*)d_in[4];
    const float* proj_w = (const float*)d_in[5];
    const float* proj_b = (const float*)d_in[6];
    float* out = (float*)d_out;

    bf16 *xh, *xl, *qh, *ql, *xrh, *xrl, *kvh, *kvl, *aoh, *aol;
    bf16 *qwh, *qwl, *kvwh, *kvwl, *srh, *srl, *prh, *prl;
    cudaGetSymbolAddress((void**)&xh,  g_xh);   cudaGetSymbolAddress((void**)&xl,  g_xl);
    cudaGetSymbolAddress((void**)&qh,  g_qh);   cudaGetSymbolAddress((void**)&ql,  g_ql);
    cudaGetSymbolAddress((void**)&xrh, g_xrh);  cudaGetSymbolAddress((void**)&xrl, g_xrl);
    cudaGetSymbolAddress((void**)&kvh, g_kvh);  cudaGetSymbolAddress((void**)&kvl, g_kvl);
    cudaGetSymbolAddress((void**)&aoh, g_aoh);  cudaGetSymbolAddress((void**)&aol, g_aol);
    cudaGetSymbolAddress((void**)&qwh, g_qwh);  cudaGetSymbolAddress((void**)&qwl, g_qwl);
    cudaGetSymbolAddress((void**)&kvwh, g_kvwh); cudaGetSymbolAddress((void**)&kvwl, g_kvwl);
    cudaGetSymbolAddress((void**)&srh, g_srh);  cudaGetSymbolAddress((void**)&srl, g_srl);
    cudaGetSymbolAddress((void**)&prh, g_prh);  cudaGetSymbolAddress((void**)&prl, g_prl);

    cudaFuncSetAttribute(hgemm<0>, cudaFuncAttributeMaxDynamicSharedMemorySize, HG_SMEM);
    cudaFuncSetAttribute(hgemm<1>, cudaFuncAttributeMaxDynamicSharedMemorySize, HG_SMEM);
    cudaFuncSetAttribute(attn_mma, cudaFuncAttributeMaxDynamicSharedMemorySize, AT_SMEM);

    // prep splits
    f2hl<<<(B_*N_*C_) / 1024, 256>>>(x, xh, xl, B_*N_*C_);
    f2hl<<<(C_*C_) / 1024, 256>>>(q_w, qwh, qwl, C_*C_);
    f2hl<<<(2*C_*C_) / 1024, 256>>>(kv_w, kvwh, kvwl, 2*C_*C_);
    f2hl<<<(C_*C_) / 1024, 256>>>(proj_w, prh, prl, C_*C_);
    srhl<<<(C_*KCONV) / 256, 256>>>(sr_w, srh, srl);

    // q projection -> bf16 h/l
    hgemm<0><<<dim3(4, 128), 256, HG_SMEM>>>(xh, xl, qwh, qwl, nullptr,
                                             nullptr, qh, ql, B_*N_, C_, C_);
    // SR conv (gathered A) -> bf16 h/l (+sr_b)
    hgemm<1><<<dim3(4, 32), 256, HG_SMEM>>>(xh, xl, srh, srl, sr_b,
                                            nullptr, xrh, xrl, B_*NK_, C_, KCONV);
    // kv projection -> bf16 h/l
    hgemm<0><<<dim3(8, 32), 256, HG_SMEM>>>(xrh, xrl, kvwh, kvwl, nullptr,
                                            nullptr, kvh, kvl, B_*NK_, 2*C_, C_);
    // attention -> bf16 h/l
    attn_mma<<<dim3(N_ / 128, 8, B_), 256, AT_SMEM>>>(qh, ql, kvh, kvl, aoh, aol);
    // output projection (+proj_b) -> fp32 d_out
    hgemm<0><<<dim3(4, 128), 256, HG_SMEM>>>(aoh, aol, prh, prl, proj_b,
                                             out, nullptr, nullptr, B_*N_, C_, C_);
}

// round 12
// speedup vs baseline: 2.6785x; 1.0792x over previous
#include <cuda_runtime.h>
#include <cuda_bf16.h>
#include <cstdint>

#define B_   4
#define N_   4096
#define C_   512
#define NK_  1024
#define KCONV 2048
typedef __nv_bfloat16 bf16;

// ---------------- scratch ----------------
__device__ bf16 g_xh [B_*N_*C_],  g_xl [B_*N_*C_];     // x split
__device__ bf16 g_qh [B_*N_*C_],  g_ql [B_*N_*C_];     // q proj
__device__ bf16 g_xrh[B_*NK_*C_], g_xrl[B_*NK_*C_];    // reduced x
__device__ bf16 g_kvh[B_*NK_*2*C_], g_kvl[B_*NK_*2*C_];
__device__ bf16 g_aoh[B_*N_*C_],  g_aol[B_*N_*C_];     // attn out
__device__ bf16 g_qwh [C_*C_],    g_qwl [C_*C_];
__device__ bf16 g_kvwh[2*C_*C_],  g_kvwl[2*C_*C_];
__device__ bf16 g_srh [C_*KCONV], g_srl [C_*KCONV];
__device__ bf16 g_prh [C_*C_],    g_prl [C_*C_];

// ---------------- helpers ----------------
__device__ __forceinline__ uint32_t s2u(const void* p){
    uint32_t a;
    asm("{ .reg .u64 t; cvta.to.shared.u64 t, %1; cvt.u32.u64 %0, t; }" : "=r"(a) : "l"(p));
    return a;
}
__device__ __forceinline__ void mma16816(float* c, const uint32_t* a, const uint32_t* b){
    asm volatile("mma.sync.aligned.m16n8k16.row.col.f32.bf16.bf16.f32 "
        "{%0,%1,%2,%3}, {%4,%5,%6,%7}, {%8,%9}, {%0,%1,%2,%3};"
        : "+f"(c[0]), "+f"(c[1]), "+f"(c[2]), "+f"(c[3])
        : "r"(a[0]), "r"(a[1]), "r"(a[2]), "r"(a[3]), "r"(b[0]), "r"(b[1]));
}
__device__ __forceinline__ void split2(float x, float y, uint32_t& h, uint32_t& l){
    __nv_bfloat162 hh = __float22bfloat162_rn(make_float2(x, y));
    float2 hf = __bfloat1622float2(hh);
    __nv_bfloat162 ll = __float22bfloat162_rn(make_float2(x - hf.x, y - hf.y));
    h = *(uint32_t*)&hh; l = *(uint32_t*)&ll;
}
__device__ __forceinline__ void ldmx4(uint32_t* r, uint32_t a){
    asm volatile("ldmatrix.sync.aligned.m8n8.x4.shared.b16 {%0,%1,%2,%3}, [%4];"
        : "=r"(r[0]), "=r"(r[1]), "=r"(r[2]), "=r"(r[3]) : "r"(a));
}
__device__ __forceinline__ void ldmx4t(uint32_t* r, uint32_t a){
    asm volatile("ldmatrix.sync.aligned.m8n8.x4.trans.shared.b16 {%0,%1,%2,%3}, [%4];"
        : "=r"(r[0]), "=r"(r[1]), "=r"(r[2]), "=r"(r[3]) : "r"(a));
}
__device__ __forceinline__ void cpa(uint32_t s, const void* g){
    asm volatile("cp.async.cg.shared.global [%0], [%1], 16;" :: "r"(s), "l"(g));
}
#define CP_COMMIT() asm volatile("cp.async.commit_group;" ::: "memory")

// ---------------- prep: fp32 -> bf16 hi/lo ----------------
__global__ void f2hl(const float* __restrict__ s, bf16* __restrict__ h,
                     bf16* __restrict__ l, int n){
    int i = (blockIdx.x * 256 + threadIdx.x) * 4;
    if (i >= n) return;
    float4 v = *reinterpret_cast<const float4*>(s + i);
    uint32_t h0, l0, h1, l1;
    split2(v.x, v.y, h0, l0);
    split2(v.z, v.w, h1, l1);
    *reinterpret_cast<uint2*>(h + i) = make_uint2(h0, h1);
    *reinterpret_cast<uint2*>(l + i) = make_uint2(l0, l1);
}
__global__ void srhl(const float* __restrict__ w, bf16* __restrict__ h,
                     bf16* __restrict__ l){
    int idx = blockIdx.x * 256 + threadIdx.x;    // over 512*2048
    int n = idx >> 11, k = idx & 2047;
    int ij = k >> 9, ci = k & 511;
    float v = w[((size_t)n * C_ + ci) * 4 + ij];
    bf16 hh = __float2bfloat16(v);
    h[idx] = hh;
    l[idx] = __float2bfloat16(v - __bfloat162float(hh));
}

// ---------------- hgemm device body ----------------
#define HG_STG   40960
#define HG_SMEM  (2 * HG_STG)

template <int MODE>
__device__ __forceinline__
void hgemm_dev(char* smc,
               const bf16* __restrict__ Ah_, const bf16* __restrict__ Al_,
               const bf16* __restrict__ Bh_, const bf16* __restrict__ Bl_,
               const float* __restrict__ bias, float* __restrict__ outF,
               bf16* __restrict__ outH, bf16* __restrict__ outL,
               int N, int K, int bx, int by) {
    const uint32_t sb = s2u(smc);
    const int tid  = threadIdx.x;
    const int lane = tid & 31, warp = tid >> 5;
    const int wm = (warp >> 2) * 64, wn = (warp & 3) * 32;

    float acc[4][4][4];
#pragma unroll
    for (int i = 0; i < 4; i++)
#pragma unroll
        for (int j = 0; j < 4; j++)
#pragma unroll
            for (int r = 0; r < 4; r++) acc[i][j][r] = 0.f;

    const int NC = K >> 5;

    auto stage_load = [&](int kci, int st){
        int k0 = kci << 5;
#pragma unroll
        for (int p = 0; p < 2; p++) {
            int id = tid + p * 256;
            int row = id >> 2, ch = id & 3;
            int kg = k0 + ch * 8;
            size_t aoff;
            if (MODE == 0) {
                aoff = (size_t)(by + row) * K + kg;
            } else {
                int m = by + row;
                int bb = m >> 10, pp = m & 1023, ph = pp >> 5, pw = pp & 31;
                int ij = kg >> 9, ci = kg & 511;
                int pix = (2 * ph + (ij >> 1)) * 64 + 2 * pw + (ij & 1);
                aoff = ((size_t)(bb << 12) + pix) * C_ + ci;
            }
            size_t boff = (size_t)(bx + row) * K + kg;
            uint32_t si = sb + st * HG_STG + row * 80 + ch * 16;
            cpa(si,         Ah_ + aoff);
            cpa(si + 10240, Al_ + aoff);
            cpa(si + 20480, Bh_ + boff);
            cpa(si + 30720, Bl_ + boff);
        }
        CP_COMMIT();
    };

    const int lm = lane >> 3, lr = lane & 7;
    const int aro = (lm & 1) * 8, aco = (lm >> 1) * 4;
    const int bro = (lm >> 1) * 8, bco = (lm & 1) * 4;

    stage_load(0, 0);

    for (int i = 0; i < NC; i++) {
        int st = i & 1;
        if (i + 1 < NC) stage_load(i + 1, st ^ 1);
        if (i + 1 < NC) asm volatile("cp.async.wait_group 1;" ::: "memory");
        else            asm volatile("cp.async.wait_group 0;" ::: "memory");
        __syncthreads();

        const uint32_t sA = sb + st * HG_STG;
#pragma unroll
        for (int kh = 0; kh < 2; kh++) {
            uint32_t ah[4][4], al[4][4], bh[2][4], bl[2][4];
#pragma unroll
            for (int mt = 0; mt < 4; mt++) {
                uint32_t ad = sA + ((wm + 16 * mt + aro + lr) * 20 + kh * 8 + aco) * 4;
                ldmx4(ah[mt], ad);
                ldmx4(al[mt], ad + 10240);
            }
#pragma unroll
            for (int ntp = 0; ntp < 2; ntp++) {
                uint32_t bd = sA + 20480 + ((wn + 16 * ntp + bro + lr) * 20 + kh * 8 + bco) * 4;
                ldmx4(bh[ntp], bd);
                ldmx4(bl[ntp], bd + 10240);
            }
#pragma unroll
            for (int mt = 0; mt < 4; mt++)
#pragma unroll
                for (int nt = 0; nt < 4; nt++) {
                    const uint32_t* ph = &bh[nt >> 1][(nt & 1) * 2];
                    const uint32_t* pl = &bl[nt >> 1][(nt & 1) * 2];
                    mma16816(acc[mt][nt], ah[mt], ph);
                    mma16816(acc[mt][nt], ah[mt], pl);
                    mma16816(acc[mt][nt], al[mt], ph);
                }
        }
        __syncthreads();
    }

    const int rq = lane >> 2, cq = 2 * (lane & 3);
#pragma unroll
    for (int mt = 0; mt < 4; mt++) {
#pragma unroll
        for (int nt = 0; nt < 4; nt++) {
            int col = bx + wn + 8 * nt + cq;
            float b0 = bias ? bias[col] : 0.f;
            float b1 = bias ? bias[col + 1] : 0.f;
            int r0 = by + wm + 16 * mt + rq;
            float v00 = acc[mt][nt][0] + b0, v01 = acc[mt][nt][1] + b1;
            float v10 = acc[mt][nt][2] + b0, v11 = acc[mt][nt][3] + b1;
            if (outF) {
                *reinterpret_cast<float2*>(outF + (size_t)r0 * N + col) = make_float2(v00, v01);
                *reinterpret_cast<float2*>(outF + (size_t)(r0 + 8) * N + col) = make_float2(v10, v11);
            }
            if (outH) {
                uint32_t h, l;
                split2(v00, v01, h, l);
                *reinterpret_cast<uint32_t*>(outH + (size_t)r0 * N + col) = h;
                *reinterpret_cast<uint32_t*>(outL + (size_t)r0 * N + col) = l;
                split2(v10, v11, h, l);
                *reinterpret_cast<uint32_t*>(outH + (size_t)(r0 + 8) * N + col) = h;
                *reinterpret_cast<uint32_t*>(outL + (size_t)(r0 + 8) * N + col) = l;
            }
        }
    }
}

template <int MODE>
__global__ __launch_bounds__(256)
void hgemm(const bf16* __restrict__ Ah_, const bf16* __restrict__ Al_,
           const bf16* __restrict__ Bh_, const bf16* __restrict__ Bl_,
           const float* __restrict__ bias, float* __restrict__ outF,
           bf16* __restrict__ outH, bf16* __restrict__ outL, int N, int K) {
    extern __shared__ char smc[];
    hgemm_dev<MODE>(smc, Ah_, Al_, Bh_, Bl_, bias, outF, outH, outL,
                    N, K, blockIdx.x * 128, blockIdx.y * 128);
}

// fused q-proj + conv launch: grid (4, 160); y<32 = conv (longer blocks first)
__global__ __launch_bounds__(256)
void hgemm_qc(const bf16* __restrict__ xh, const bf16* __restrict__ xl,
              const bf16* __restrict__ srh, const bf16* __restrict__ srl,
              const float* __restrict__ sr_b,
              bf16* __restrict__ xrh, bf16* __restrict__ xrl,
              const bf16* __restrict__ qwh, const bf16* __restrict__ qwl,
              bf16* __restrict__ qh, bf16* __restrict__ ql) {
    extern __shared__ char smc[];
    if (blockIdx.y < 32)
        hgemm_dev<1>(smc, xh, xl, srh, srl, sr_b, nullptr, xrh, xrl,
                     C_, KCONV, blockIdx.x * 128, blockIdx.y * 128);
    else
        hgemm_dev<0>(smc, xh, xl, qwh, qwl, nullptr, nullptr, qh, ql,
                     C_, C_, blockIdx.x * 128, (blockIdx.y - 32) * 128);
}

// ---------------- pipelined tensor-core flash attention ----------------
// 128 q x (b,h); 8 warps x 16 q; K/V tiles of 64 keys, cp.async 2-stage.
// SMEM 73728B: [0,36864) = Q then stage1; [36864,73728) = stage0.
// Stage layout (u32): Kh[64*36] Kl Vh Vl (2304 each).
#define AT_SMEM (2 * 36864)

__global__ __launch_bounds__(256)
void attn_mma(const bf16* __restrict__ Qh_, const bf16* __restrict__ Ql_,
              const bf16* __restrict__ KVh_, const bf16* __restrict__ KVl_,
              bf16* __restrict__ Oh, bf16* __restrict__ Ol) {
    extern __shared__ uint32_t su[];
    const uint32_t sb = s2u(su);

    const int tid  = threadIdx.x;
    const int lane = tid & 31, warp = tid >> 5;
    const int rq = lane >> 2, tq = lane & 3;
    const int qb = blockIdx.x * 128;
    const int h  = blockIdx.y;
    const int b  = blockIdx.z;

    const int lm = lane >> 3, lr = lane & 7;
    const int aro = (lm & 1) * 8, aco = (lm >> 1) * 4;
    const int bro = (lm >> 1) * 8, bco = (lm & 1) * 4;
    const int vro = (lm & 1) * 8, vns = (lm >> 1);

    // ---- load Q tile [128 q][64 d] h/l into su[0..9216) u32 ----
    {
        size_t qo = ((size_t)(b * N_ + qb)) * C_ + h * 64;
#pragma unroll
        for (int p = 0; p < 8; p++) {
            int id = tid + p * 256;                 // 0..2047
            int arr = id >> 10, rem = id & 1023;
            int row = rem >> 3, ch = rem & 7;
            const bf16* src = (arr ? Ql_ : Qh_) + qo + (size_t)row * C_ + ch * 8;
            uint32_t* dst = su + arr * 4608 + row * 36 + ch * 4;
            *reinterpret_cast<uint4*>(dst) = *reinterpret_cast<const uint4*>(src);
        }
    }
    __syncthreads();

    // ---- Q fragments in registers (smem Q area becomes stage1 afterwards) ----
    uint32_t qah[4][4], qal[4][4];
#pragma unroll
    for (int kc = 0; kc < 4; kc++) {
        uint32_t ad = sb + ((warp * 16 + aro + lr) * 36 + kc * 8 + aco) * 4;
        ldmx4(qah[kc], ad);
        ldmx4(qal[kc], ad + 4608 * 4);
    }

    float oacc[8][4];
#pragma unroll
    for (int nt = 0; nt < 8; nt++)
#pragma unroll
        for (int r = 0; r < 4; r++) oacc[nt][r] = 0.f;
    float m0 = -1e30f, m1 = -1e30f, l0 = 0.f, l1 = 0.f;

    const size_t kvo = (size_t)b * NK_ * (2 * C_) + h * 64;

    auto kv_load = [&](int t, uint32_t dstb){
#pragma unroll
        for (int p = 0; p < 8; p++) {
            int id = tid + p * 256;                 // 0..2047
            int arr = id >> 9, rem = id & 511;
            int row = rem >> 3, ch = rem & 7;
            const bf16* base = (arr & 1) ? KVl_ : KVh_;
            size_t off = kvo + (size_t)(t * 64 + row) * (2 * C_) + ((arr >> 1) ? C_ : 0) + ch * 8;
            cpa(dstb + (arr * 2304 + row * 36 + ch * 4) * 4, base + off);
        }
        CP_COMMIT();
    };

    kv_load(0, sb + 36864);                         // tile 0 -> stage0

    for (int t = 0; t < NK_ / 64; t++) {
        const uint32_t cb = (t & 1) ? sb : sb + 36864;      // compute stage
        asm volatile("cp.async.wait_group 0;" ::: "memory");
        __syncthreads();
        if (t + 1 < NK_ / 64)
            kv_load(t + 1, (t & 1) ? sb + 36864 : sb);      // prefetch other stage

        // ---- S = Q K^T ----
        float sacc[8][4];
#pragma unroll
        for (int nt = 0; nt < 8; nt++)
#pragma unroll
            for (int r = 0; r < 4; r++) sacc[nt][r] = 0.f;
#pragma unroll
        for (int kc = 0; kc < 4; kc++) {
#pragma unroll
            for (int ntp = 0; ntp < 4; ntp++) {
                uint32_t bh4[4], bl4[4];
                uint32_t bd = cb + ((16 * ntp + bro + lr) * 36 + kc * 8 + bco) * 4;
                ldmx4(bh4, bd);
                ldmx4(bl4, bd + 9216);
#pragma unroll
                for (int s = 0; s < 2; s++) {
                    mma16816(sacc[2 * ntp + s], qah[kc], &bh4[s * 2]);
                    mma16816(sacc[2 * ntp + s], qah[kc], &bl4[s * 2]);
                    mma16816(sacc[2 * ntp + s], qal[kc], &bh4[s * 2]);
                }
            }
        }

        // ---- online softmax ----
        float tm0 = -1e30f, tm1 = -1e30f;
#pragma unroll
        for (int nt = 0; nt < 8; nt++) {
            tm0 = fmaxf(tm0, fmaxf(sacc[nt][0], sacc[nt][1]));
            tm1 = fmaxf(tm1, fmaxf(sacc[nt][2], sacc[nt][3]));
        }
#pragma unroll
        for (int o = 1; o <= 2; o <<= 1) {
            tm0 = fmaxf(tm0, __shfl_xor_sync(0xffffffffu, tm0, o));
            tm1 = fmaxf(tm1, __shfl_xor_sync(0xffffffffu, tm1, o));
        }
        float mn0 = fmaxf(m0, tm0), mn1 = fmaxf(m1, tm1);
        float al0 = __expf(0.125f * (m0 - mn0));
        float al1 = __expf(0.125f * (m1 - mn1));
        float rs0 = 0.f, rs1 = 0.f;
#pragma unroll
        for (int nt = 0; nt < 8; nt++) {
            float p0 = __expf(0.125f * (sacc[nt][0] - mn0));
            float p1 = __expf(0.125f * (sacc[nt][1] - mn0));
            float p2 = __expf(0.125f * (sacc[nt][2] - mn1));
            float p3 = __expf(0.125f * (sacc[nt][3] - mn1));
            sacc[nt][0] = p0; sacc[nt][1] = p1; sacc[nt][2] = p2; sacc[nt][3] = p3;
            rs0 += p0 + p1; rs1 += p2 + p3;
        }
#pragma unroll
        for (int o = 1; o <= 2; o <<= 1) {
            rs0 += __shfl_xor_sync(0xffffffffu, rs0, o);
            rs1 += __shfl_xor_sync(0xffffffffu, rs1, o);
        }
        l0 = l0 * al0 + rs0;  l1 = l1 * al1 + rs1;
        m0 = mn0;             m1 = mn1;
#pragma unroll
        for (int nt = 0; nt < 8; nt++) {
            oacc[nt][0] *= al0; oacc[nt][1] *= al0;
            oacc[nt][2] *= al1; oacc[nt][3] *= al1;
        }

        // ---- P -> A-frags (registers only) ----
        uint32_t pah[4][4], pal[4][4];
#pragma unroll
        for (int kc = 0; kc < 4; kc++) {
            split2(sacc[2*kc][0],   sacc[2*kc][1],   pah[kc][0], pal[kc][0]);
            split2(sacc[2*kc][2],   sacc[2*kc][3],   pah[kc][1], pal[kc][1]);
            split2(sacc[2*kc+1][0], sacc[2*kc+1][1], pah[kc][2], pal[kc][2]);
            split2(sacc[2*kc+1][2], sacc[2*kc+1][3], pah[kc][3], pal[kc][3]);
        }

        // ---- O += P V ----
#pragma unroll
        for (int kc = 0; kc < 4; kc++) {
#pragma unroll
            for (int ntp = 0; ntp < 4; ntp++) {
                uint32_t vh4[4], vl4[4];
                uint32_t vd = cb + 18432 + ((16 * kc + vro + lr) * 36 + (2 * ntp + vns) * 4) * 4;
                ldmx4t(vh4, vd);
                ldmx4t(vl4, vd + 9216);
#pragma unroll
                for (int s = 0; s < 2; s++) {
                    mma16816(oacc[2 * ntp + s], pah[kc], &vh4[s * 2]);
                    mma16816(oacc[2 * ntp + s], pal[kc], &vh4[s * 2]);
                    mma16816(oacc[2 * ntp + s], pah[kc], &vl4[s * 2]);
                }
            }
        }
    }

    // ---- epilogue -> bf16 h/l ----
    float inv0 = 1.f / l0, inv1 = 1.f / l1;
    int row0 = qb + warp * 16 + rq;
    size_t ob = (size_t)(b * N_) * C_ + h * 64;
#pragma unroll
    for (int nt = 0; nt < 8; nt++) {
        int d = 8 * nt + 2 * tq;
        uint32_t hh, ll;
        split2(oacc[nt][0] * inv0, oacc[nt][1] * inv0, hh, ll);
        *reinterpret_cast<uint32_t*>(Oh + ob + (size_t)row0 * C_ + d) = hh;
        *reinterpret_cast<uint32_t*>(Ol + ob + (size_t)row0 * C_ + d) = ll;
        split2(oacc[nt][2] * inv1, oacc[nt][3] * inv1, hh, ll);
        *reinterpret_cast<uint32_t*>(Oh + ob + (size_t)(row0 + 8) * C_ + d) = hh;
        *reinterpret_cast<uint32_t*>(Ol + ob + (size_t)(row0 + 8) * C_ + d) = ll;
    }
}

// ---------------- launch ----------------
extern "C" void kernel_launch(void* const* d_in, const int* in_sizes, int n_in,
                              void* d_out, int out_size) {
    const float* x      = (const float*)d_in[0];
    const float* q_w    = (const float*)d_in[1];
    const float* kv_w   = (const float*)d_in[2];
    const float* sr_w   = (const float*)d_in[3];
    const float* sr_b   = (const float*)d_in[4];
    const float* proj_w = (const float*)d_in[5];
    const float* proj_b = (const float*)d_in[6];
    float* out = (float*)d_out;

    bf16 *xh, *xl, *qh, *ql, *xrh, *xrl, *kvh, *kvl, *aoh, *aol;
    bf16 *qwh, *qwl, *kvwh, *kvwl, *srh, *srl, *prh, *prl;
    cudaGetSymbolAddress((void**)&xh,  g_xh);   cudaGetSymbolAddress((void**)&xl,  g_xl);
    cudaGetSymbolAddress((void**)&qh,  g_qh);   cudaGetSymbolAddress((void**)&ql,  g_ql);
    cudaGetSymbolAddress((void**)&xrh, g_xrh);  cudaGetSymbolAddress((void**)&xrl, g_xrl);
    cudaGetSymbolAddress((void**)&kvh, g_kvh);  cudaGetSymbolAddress((void**)&kvl, g_kvl);
    cudaGetSymbolAddress((void**)&aoh, g_aoh);  cudaGetSymbolAddress((void**)&aol, g_aol);
    cudaGetSymbolAddress((void**)&qwh, g_qwh);  cudaGetSymbolAddress((void**)&qwl, g_qwl);
    cudaGetSymbolAddress((void**)&kvwh, g_kvwh); cudaGetSymbolAddress((void**)&kvwl, g_kvwl);
    cudaGetSymbolAddress((void**)&srh, g_srh);  cudaGetSymbolAddress((void**)&srl, g_srl);
    cudaGetSymbolAddress((void**)&prh, g_prh);  cudaGetSymbolAddress((void**)&prl, g_prl);

    cudaFuncSetAttribute(hgemm<0>, cudaFuncAttributeMaxDynamicSharedMemorySize, HG_SMEM);
    cudaFuncSetAttribute(hgemm_qc, cudaFuncAttributeMaxDynamicSharedMemorySize, HG_SMEM);
    cudaFuncSetAttribute(attn_mma, cudaFuncAttributeMaxDynamicSharedMemorySize, AT_SMEM);

    // prep splits
    f2hl<<<(B_*N_*C_) / 1024, 256>>>(x, xh, xl, B_*N_*C_);
    f2hl<<<(C_*C_) / 1024, 256>>>(q_w, qwh, qwl, C_*C_);
    f2hl<<<(2*C_*C_) / 1024, 256>>>(kv_w, kvwh, kvwl, 2*C_*C_);
    f2hl<<<(C_*C_) / 1024, 256>>>(proj_w, prh, prl, C_*C_);
    srhl<<<(C_*KCONV) / 256, 256>>>(sr_w, srh, srl);

    // fused conv + q-proj (conv blocks first: y<32)
    hgemm_qc<<<dim3(4, 160), 256, HG_SMEM>>>(xh, xl, srh, srl, sr_b, xrh, xrl,
                                             qwh, qwl, qh, ql);
    // kv projection -> bf16 h/l
    hgemm<0><<<dim3(8, 32), 256, HG_SMEM>>>(xrh, xrl, kvwh, kvwl, nullptr,
                                            nullptr, kvh, kvl, 2*C_, C_);
    // attention -> bf16 h/l
    attn_mma<<<dim3(N_ / 128, 8, B_), 256, AT_SMEM>>>(qh, ql, kvh, kvl, aoh, aol);
    // output projection (+proj_b) -> fp32 d_out
    hgemm<0><<<dim3(4, 128), 256, HG_SMEM>>>(aoh, aol, prh, prl, proj_b,
                                             out, nullptr, nullptr, C_, C_);
}

// round 13
// speedup vs baseline: 2.6978x; 1.0072x over previous
#include <cuda_runtime.h>
#include <cuda_bf16.h>
#include <cstdint>

#define B_   4
#define N_   4096
#define C_   512
#define NK_  1024
#define KCONV 2048
typedef __nv_bfloat16 bf16;

// ---------------- scratch ----------------
__device__ bf16 g_xh [B_*N_*C_],  g_xl [B_*N_*C_];
__device__ bf16 g_qh [B_*N_*C_],  g_ql [B_*N_*C_];
__device__ bf16 g_xrh[B_*NK_*C_], g_xrl[B_*NK_*C_];
__device__ bf16 g_kvh[B_*NK_*2*C_], g_kvl[B_*NK_*2*C_];
__device__ bf16 g_aoh[B_*N_*C_],  g_aol[B_*N_*C_];
__device__ bf16 g_qwh [C_*C_],    g_qwl [C_*C_];
__device__ bf16 g_kvwh[2*C_*C_],  g_kvwl[2*C_*C_];
__device__ bf16 g_srh [C_*KCONV], g_srl [C_*KCONV];
__device__ bf16 g_prh [C_*C_],    g_prl [C_*C_];

// ---------------- helpers ----------------
__device__ __forceinline__ uint32_t s2u(const void* p){
    uint32_t a;
    asm("{ .reg .u64 t; cvta.to.shared.u64 t, %1; cvt.u32.u64 %0, t; }" : "=r"(a) : "l"(p));
    return a;
}
__device__ __forceinline__ void mma16816(float* c, const uint32_t* a, const uint32_t* b){
    asm volatile("mma.sync.aligned.m16n8k16.row.col.f32.bf16.bf16.f32 "
        "{%0,%1,%2,%3}, {%4,%5,%6,%7}, {%8,%9}, {%0,%1,%2,%3};"
        : "+f"(c[0]), "+f"(c[1]), "+f"(c[2]), "+f"(c[3])
        : "r"(a[0]), "r"(a[1]), "r"(a[2]), "r"(a[3]), "r"(b[0]), "r"(b[1]));
}
__device__ __forceinline__ void split2(float x, float y, uint32_t& h, uint32_t& l){
    __nv_bfloat162 hh = __float22bfloat162_rn(make_float2(x, y));
    float2 hf = __bfloat1622float2(hh);
    __nv_bfloat162 ll = __float22bfloat162_rn(make_float2(x - hf.x, y - hf.y));
    h = *(uint32_t*)&hh; l = *(uint32_t*)&ll;
}
__device__ __forceinline__ void ldmx4(uint32_t* r, uint32_t a){
    asm volatile("ldmatrix.sync.aligned.m8n8.x4.shared.b16 {%0,%1,%2,%3}, [%4];"
        : "=r"(r[0]), "=r"(r[1]), "=r"(r[2]), "=r"(r[3]) : "r"(a));
}
__device__ __forceinline__ void ldmx4t(uint32_t* r, uint32_t a){
    asm volatile("ldmatrix.sync.aligned.m8n8.x4.trans.shared.b16 {%0,%1,%2,%3}, [%4];"
        : "=r"(r[0]), "=r"(r[1]), "=r"(r[2]), "=r"(r[3]) : "r"(a));
}
__device__ __forceinline__ void cpa(uint32_t s, const void* g){
    asm volatile("cp.async.cg.shared.global [%0], [%1], 16;" :: "r"(s), "l"(g));
}
#define CP_COMMIT() asm volatile("cp.async.commit_group;" ::: "memory")

// ---------------- prep: fp32 -> bf16 hi/lo ----------------
__global__ void f2hl(const float* __restrict__ s, bf16* __restrict__ h,
                     bf16* __restrict__ l, int n){
    int i = (blockIdx.x * 256 + threadIdx.x) * 4;
    if (i >= n) return;
    float4 v = *reinterpret_cast<const float4*>(s + i);
    uint32_t h0, l0, h1, l1;
    split2(v.x, v.y, h0, l0);
    split2(v.z, v.w, h1, l1);
    *reinterpret_cast<uint2*>(h + i) = make_uint2(h0, h1);
    *reinterpret_cast<uint2*>(l + i) = make_uint2(l0, l1);
}
__global__ void srhl(const float* __restrict__ w, bf16* __restrict__ h,
                     bf16* __restrict__ l){
    int idx = blockIdx.x * 256 + threadIdx.x;    // over 512*2048
    int n = idx >> 11, k = idx & 2047;
    int ij = k >> 9, ci = k & 511;
    float v = w[((size_t)n * C_ + ci) * 4 + ij];
    bf16 hh = __float2bfloat16(v);
    h[idx] = hh;
    l[idx] = __float2bfloat16(v - __bfloat162float(hh));
}

// ---------------- hgemm device body ----------------
#define HG_STG   40960
#define HG_SMEM  (2 * HG_STG)

template <int MODE>
__device__ __forceinline__
void hgemm_dev(char* smc,
               const bf16* __restrict__ Ah_, const bf16* __restrict__ Al_,
               const bf16* __restrict__ Bh_, const bf16* __restrict__ Bl_,
               const float* __restrict__ bias, float* __restrict__ outF,
               bf16* __restrict__ outH, bf16* __restrict__ outL,
               int N, int K, int bx, int by) {
    const uint32_t sb = s2u(smc);
    const int tid  = threadIdx.x;
    const int lane = tid & 31, warp = tid >> 5;
    const int wm = (warp >> 2) * 64, wn = (warp & 3) * 32;

    float acc[4][4][4];
#pragma unroll
    for (int i = 0; i < 4; i++)
#pragma unroll
        for (int j = 0; j < 4; j++)
#pragma unroll
            for (int r = 0; r < 4; r++) acc[i][j][r] = 0.f;

    const int NC = K >> 5;

    auto stage_load = [&](int kci, int st){
        int k0 = kci << 5;
#pragma unroll
        for (int p = 0; p < 2; p++) {
            int id = tid + p * 256;
            int row = id >> 2, ch = id & 3;
            int kg = k0 + ch * 8;
            size_t aoff;
            if (MODE == 0) {
                aoff = (size_t)(by + row) * K + kg;
            } else {
                int m = by + row;
                int bb = m >> 10, pp = m & 1023, ph = pp >> 5, pw = pp & 31;
                int ij = kg >> 9, ci = kg & 511;
                int pix = (2 * ph + (ij >> 1)) * 64 + 2 * pw + (ij & 1);
                aoff = ((size_t)(bb << 12) + pix) * C_ + ci;
            }
            size_t boff = (size_t)(bx + row) * K + kg;
            uint32_t si = sb + st * HG_STG + row * 80 + ch * 16;
            cpa(si,         Ah_ + aoff);
            cpa(si + 10240, Al_ + aoff);
            cpa(si + 20480, Bh_ + boff);
            cpa(si + 30720, Bl_ + boff);
        }
        CP_COMMIT();
    };

    const int lm = lane >> 3, lr = lane & 7;
    const int aro = (lm & 1) * 8, aco = (lm >> 1) * 4;
    const int bro = (lm >> 1) * 8, bco = (lm & 1) * 4;

    stage_load(0, 0);

    for (int i = 0; i < NC; i++) {
        int st = i & 1;
        if (i + 1 < NC) stage_load(i + 1, st ^ 1);
        if (i + 1 < NC) asm volatile("cp.async.wait_group 1;" ::: "memory");
        else            asm volatile("cp.async.wait_group 0;" ::: "memory");
        __syncthreads();

        const uint32_t sA = sb + st * HG_STG;
#pragma unroll
        for (int kh = 0; kh < 2; kh++) {
            uint32_t ah[4][4], al[4][4], bh[2][4], bl[2][4];
#pragma unroll
            for (int mt = 0; mt < 4; mt++) {
                uint32_t ad = sA + ((wm + 16 * mt + aro + lr) * 20 + kh * 8 + aco) * 4;
                ldmx4(ah[mt], ad);
                ldmx4(al[mt], ad + 10240);
            }
#pragma unroll
            for (int ntp = 0; ntp < 2; ntp++) {
                uint32_t bd = sA + 20480 + ((wn + 16 * ntp + bro + lr) * 20 + kh * 8 + bco) * 4;
                ldmx4(bh[ntp], bd);
                ldmx4(bl[ntp], bd + 10240);
            }
            // term-outer ordering: 16 independent MMAs per term
#pragma unroll
            for (int mt = 0; mt < 4; mt++)
#pragma unroll
                for (int nt = 0; nt < 4; nt++)
                    mma16816(acc[mt][nt], ah[mt], &bh[nt >> 1][(nt & 1) * 2]);
#pragma unroll
            for (int mt = 0; mt < 4; mt++)
#pragma unroll
                for (int nt = 0; nt < 4; nt++)
                    mma16816(acc[mt][nt], ah[mt], &bl[nt >> 1][(nt & 1) * 2]);
#pragma unroll
            for (int mt = 0; mt < 4; mt++)
#pragma unroll
                for (int nt = 0; nt < 4; nt++)
                    mma16816(acc[mt][nt], al[mt], &bh[nt >> 1][(nt & 1) * 2]);
        }
        __syncthreads();
    }

    const int rq = lane >> 2, cq = 2 * (lane & 3);
#pragma unroll
    for (int mt = 0; mt < 4; mt++) {
#pragma unroll
        for (int nt = 0; nt < 4; nt++) {
            int col = bx + wn + 8 * nt + cq;
            float b0 = bias ? bias[col] : 0.f;
            float b1 = bias ? bias[col + 1] : 0.f;
            int r0 = by + wm + 16 * mt + rq;
            float v00 = acc[mt][nt][0] + b0, v01 = acc[mt][nt][1] + b1;
            float v10 = acc[mt][nt][2] + b0, v11 = acc[mt][nt][3] + b1;
            if (outF) {
                *reinterpret_cast<float2*>(outF + (size_t)r0 * N + col) = make_float2(v00, v01);
                *reinterpret_cast<float2*>(outF + (size_t)(r0 + 8) * N + col) = make_float2(v10, v11);
            }
            if (outH) {
                uint32_t h, l;
                split2(v00, v01, h, l);
                *reinterpret_cast<uint32_t*>(outH + (size_t)r0 * N + col) = h;
                *reinterpret_cast<uint32_t*>(outL + (size_t)r0 * N + col) = l;
                split2(v10, v11, h, l);
                *reinterpret_cast<uint32_t*>(outH + (size_t)(r0 + 8) * N + col) = h;
                *reinterpret_cast<uint32_t*>(outL + (size_t)(r0 + 8) * N + col) = l;
            }
        }
    }
}

template <int MODE>
__global__ __launch_bounds__(256)
void hgemm(const bf16* __restrict__ Ah_, const bf16* __restrict__ Al_,
           const bf16* __restrict__ Bh_, const bf16* __restrict__ Bl_,
           const float* __restrict__ bias, float* __restrict__ outF,
           bf16* __restrict__ outH, bf16* __restrict__ outL, int N, int K) {
    extern __shared__ char smc[];
    hgemm_dev<MODE>(smc, Ah_, Al_, Bh_, Bl_, bias, outF, outH, outL,
                    N, K, blockIdx.x * 128, blockIdx.y * 128);
}

// fused q-proj + conv launch: grid (4, 160); y<32 = conv (longer blocks first)
__global__ __launch_bounds__(256)
void hgemm_qc(const bf16* __restrict__ xh, const bf16* __restrict__ xl,
              const bf16* __restrict__ srh, const bf16* __restrict__ srl,
              const float* __restrict__ sr_b,
              bf16* __restrict__ xrh, bf16* __restrict__ xrl,
              const bf16* __restrict__ qwh, const bf16* __restrict__ qwl,
              bf16* __restrict__ qh, bf16* __restrict__ ql) {
    extern __shared__ char smc[];
    if (blockIdx.y < 32)
        hgemm_dev<1>(smc, xh, xl, srh, srl, sr_b, nullptr, xrh, xrl,
                     C_, KCONV, blockIdx.x * 128, blockIdx.y * 128);
    else
        hgemm_dev<0>(smc, xh, xl, qwh, qwl, nullptr, nullptr, qh, ql,
                     C_, C_, blockIdx.x * 128, (blockIdx.y - 32) * 128);
}

// ---------------- pipelined tensor-core flash attention ----------------
#define AT_SMEM (2 * 36864)

__global__ __launch_bounds__(256)
void attn_mma(const bf16* __restrict__ Qh_, const bf16* __restrict__ Ql_,
              const bf16* __restrict__ KVh_, const bf16* __restrict__ KVl_,
              bf16* __restrict__ Oh, bf16* __restrict__ Ol) {
    extern __shared__ uint32_t su[];
    const uint32_t sb = s2u(su);

    const int tid  = threadIdx.x;
    const int lane = tid & 31, warp = tid >> 5;
    const int rq = lane >> 2, tq = lane & 3;
    const int qb = blockIdx.x * 128;
    const int h  = blockIdx.y;
    const int b  = blockIdx.z;

    const int lm = lane >> 3, lr = lane & 7;
    const int aro = (lm & 1) * 8, aco = (lm >> 1) * 4;
    const int bro = (lm >> 1) * 8, bco = (lm & 1) * 4;
    const int vro = (lm & 1) * 8, vns = (lm >> 1);

    // ---- load Q tile [128 q][64 d] h/l into su[0..9216) u32 ----
    {
        size_t qo = ((size_t)(b * N_ + qb)) * C_ + h * 64;
#pragma unroll
        for (int p = 0; p < 8; p++) {
            int id = tid + p * 256;
            int arr = id >> 10, rem = id & 1023;
            int row = rem >> 3, ch = rem & 7;
            const bf16* src = (arr ? Ql_ : Qh_) + qo + (size_t)row * C_ + ch * 8;
            uint32_t* dst = su + arr * 4608 + row * 36 + ch * 4;
            *reinterpret_cast<uint4*>(dst) = *reinterpret_cast<const uint4*>(src);
        }
    }
    __syncthreads();

    // ---- Q fragments in registers ----
    uint32_t qah[4][4], qal[4][4];
#pragma unroll
    for (int kc = 0; kc < 4; kc++) {
        uint32_t ad = sb + ((warp * 16 + aro + lr) * 36 + kc * 8 + aco) * 4;
        ldmx4(qah[kc], ad);
        ldmx4(qal[kc], ad + 4608 * 4);
    }

    float oacc[8][4];
#pragma unroll
    for (int nt = 0; nt < 8; nt++)
#pragma unroll
        for (int r = 0; r < 4; r++) oacc[nt][r] = 0.f;
    float m0 = -1e30f, m1 = -1e30f, l0 = 0.f, l1 = 0.f;

    const size_t kvo = (size_t)b * NK_ * (2 * C_) + h * 64;

    auto kv_load = [&](int t, uint32_t dstb){
#pragma unroll
        for (int p = 0; p < 8; p++) {
            int id = tid + p * 256;
            int arr = id >> 9, rem = id & 511;
            int row = rem >> 3, ch = rem & 7;
            const bf16* base = (arr & 1) ? KVl_ : KVh_;
            size_t off = kvo + (size_t)(t * 64 + row) * (2 * C_) + ((arr >> 1) ? C_ : 0) + ch * 8;
            cpa(dstb + (arr * 2304 + row * 36 + ch * 4) * 4, base + off);
        }
        CP_COMMIT();
    };

    kv_load(0, sb + 36864);

    for (int t = 0; t < NK_ / 64; t++) {
        const uint32_t cb = (t & 1) ? sb : sb + 36864;
        asm volatile("cp.async.wait_group 0;" ::: "memory");
        __syncthreads();
        if (t + 1 < NK_ / 64)
            kv_load(t + 1, (t & 1) ? sb + 36864 : sb);

        // ---- S = Q K^T (term-outer within ntp pairs) ----
        float sacc[8][4];
#pragma unroll
        for (int nt = 0; nt < 8; nt++)
#pragma unroll
            for (int r = 0; r < 4; r++) sacc[nt][r] = 0.f;
#pragma unroll
        for (int kc = 0; kc < 4; kc++) {
#pragma unroll
            for (int ng = 0; ng < 2; ng++) {          // ntp pair {2ng, 2ng+1}
                uint32_t bh4[2][4], bl4[2][4];
#pragma unroll
                for (int j = 0; j < 2; j++) {
                    uint32_t bd = cb + ((16 * (2 * ng + j) + bro + lr) * 36 + kc * 8 + bco) * 4;
                    ldmx4(bh4[j], bd);
                    ldmx4(bl4[j], bd + 9216);
                }
#pragma unroll
                for (int j = 0; j < 2; j++)
#pragma unroll
                    for (int s = 0; s < 2; s++)
                        mma16816(sacc[2 * (2 * ng + j) + s], qah[kc], &bh4[j][s * 2]);
#pragma unroll
                for (int j = 0; j < 2; j++)
#pragma unroll
                    for (int s = 0; s < 2; s++)
                        mma16816(sacc[2 * (2 * ng + j) + s], qah[kc], &bl4[j][s * 2]);
#pragma unroll
                for (int j = 0; j < 2; j++)
#pragma unroll
                    for (int s = 0; s < 2; s++)
                        mma16816(sacc[2 * (2 * ng + j) + s], qal[kc], &bh4[j][s * 2]);
            }
        }

        // ---- online softmax ----
        float tm0 = -1e30f, tm1 = -1e30f;
#pragma unroll
        for (int nt = 0; nt < 8; nt++) {
            tm0 = fmaxf(tm0, fmaxf(sacc[nt][0], sacc[nt][1]));
            tm1 = fmaxf(tm1, fmaxf(sacc[nt][2], sacc[nt][3]));
        }
#pragma unroll
        for (int o = 1; o <= 2; o <<= 1) {
            tm0 = fmaxf(tm0, __shfl_xor_sync(0xffffffffu, tm0, o));
            tm1 = fmaxf(tm1, __shfl_xor_sync(0xffffffffu, tm1, o));
        }
        float mn0 = fmaxf(m0, tm0), mn1 = fmaxf(m1, tm1);
        float al0 = __expf(0.125f * (m0 - mn0));
        float al1 = __expf(0.125f * (m1 - mn1));
        float rs0 = 0.f, rs1 = 0.f;
#pragma unroll
        for (int nt = 0; nt < 8; nt++) {
            float p0 = __expf(0.125f * (sacc[nt][0] - mn0));
            float p1 = __expf(0.125f * (sacc[nt][1] - mn0));
            float p2 = __expf(0.125f * (sacc[nt][2] - mn1));
            float p3 = __expf(0.125f * (sacc[nt][3] - mn1));
            sacc[nt][0] = p0; sacc[nt][1] = p1; sacc[nt][2] = p2; sacc[nt][3] = p3;
            rs0 += p0 + p1; rs1 += p2 + p3;
        }
#pragma unroll
        for (int o = 1; o <= 2; o <<= 1) {
            rs0 += __shfl_xor_sync(0xffffffffu, rs0, o);
            rs1 += __shfl_xor_sync(0xffffffffu, rs1, o);
        }
        l0 = l0 * al0 + rs0;  l1 = l1 * al1 + rs1;
        m0 = mn0;             m1 = mn1;
#pragma unroll
        for (int nt = 0; nt < 8; nt++) {
            oacc[nt][0] *= al0; oacc[nt][1] *= al0;
            oacc[nt][2] *= al1; oacc[nt][3] *= al1;
        }

        // ---- P -> A-frags (registers only) ----
        uint32_t pah[4][4], pal[4][4];
#pragma unroll
        for (int kc = 0; kc < 4; kc++) {
            split2(sacc[2*kc][0],   sacc[2*kc][1],   pah[kc][0], pal[kc][0]);
            split2(sacc[2*kc][2],   sacc[2*kc][3],   pah[kc][1], pal[kc][1]);
            split2(sacc[2*kc+1][0], sacc[2*kc+1][1], pah[kc][2], pal[kc][2]);
            split2(sacc[2*kc+1][2], sacc[2*kc+1][3], pah[kc][3], pal[kc][3]);
        }

        // ---- O += P V (term-outer within ntp pairs) ----
#pragma unroll
        for (int kc = 0; kc < 4; kc++) {
#pragma unroll
            for (int ng = 0; ng < 2; ng++) {
                uint32_t vh4[2][4], vl4[2][4];
#pragma unroll
                for (int j = 0; j < 2; j++) {
                    uint32_t vd = cb + 18432 +
                        ((16 * kc + vro + lr) * 36 + (2 * (2 * ng + j) + vns) * 4) * 4;
                    ldmx4t(vh4[j], vd);
                    ldmx4t(vl4[j], vd + 9216);
                }
#pragma unroll
                for (int j = 0; j < 2; j++)
#pragma unroll
                    for (int s = 0; s < 2; s++)
                        mma16816(oacc[2 * (2 * ng + j) + s], pah[kc], &vh4[j][s * 2]);
#pragma unroll
                for (int j = 0; j < 2; j++)
#pragma unroll
                    for (int s = 0; s < 2; s++)
                        mma16816(oacc[2 * (2 * ng + j) + s], pal[kc], &vh4[j][s * 2]);
#pragma unroll
                for (int j = 0; j < 2; j++)
#pragma unroll
                    for (int s = 0; s < 2; s++)
                        mma16816(oacc[2 * (2 * ng + j) + s], pah[kc], &vl4[j][s * 2]);
            }
        }
    }

    // ---- epilogue -> bf16 h/l ----
    float inv0 = 1.f / l0, inv1 = 1.f / l1;
    int row0 = qb + warp * 16 + rq;
    size_t ob = (size_t)(b * N_) * C_ + h * 64;
#pragma unroll
    for (int nt = 0; nt < 8; nt++) {
        int d = 8 * nt + 2 * tq;
        uint32_t hh, ll;
        split2(oacc[nt][0] * inv0, oacc[nt][1] * inv0, hh, ll);
        *reinterpret_cast<uint32_t*>(Oh + ob + (size_t)row0 * C_ + d) = hh;
        *reinterpret_cast<uint32_t*>(Ol + ob + (size_t)row0 * C_ + d) = ll;
        split2(oacc[nt][2] * inv1, oacc[nt][3] * inv1, hh, ll);
        *reinterpret_cast<uint32_t*>(Oh + ob + (size_t)(row0 + 8) * C_ + d) = hh;
        *reinterpret_cast<uint32_t*>(Ol + ob + (size_t)(row0 + 8) * C_ + d) = ll;
    }
}

// ---------------- launch ----------------
extern "C" void kernel_launch(void* const* d_in, const int* in_sizes, int n_in,
                              void* d_out, int out_size) {
    const float* x      = (const float*)d_in[0];
    const float* q_w    = (const float*)d_in[1];
    const float* kv_w   = (const float*)d_in[2];
    const float* sr_w   = (const float*)d_in[3];
    const float* sr_b   = (const float*)d_in[4];
    const float* proj_w = (const float*)d_in[5];
    const float* proj_b = (const float*)d_in[6];
    float* out = (float*)d_out;

    bf16 *xh, *xl, *qh, *ql, *xrh, *xrl, *kvh, *kvl, *aoh, *aol;
    bf16 *qwh, *qwl, *kvwh, *kvwl, *srh, *srl, *prh, *prl;
    cudaGetSymbolAddress((void**)&xh,  g_xh);   cudaGetSymbolAddress((void**)&xl,  g_xl);
    cudaGetSymbolAddress((void**)&qh,  g_qh);   cudaGetSymbolAddress((void**)&ql,  g_ql);
    cudaGetSymbolAddress((void**)&xrh, g_xrh);  cudaGetSymbolAddress((void**)&xrl, g_xrl);
    cudaGetSymbolAddress((void**)&kvh, g_kvh);  cudaGetSymbolAddress((void**)&kvl, g_kvl);
    cudaGetSymbolAddress((void**)&aoh, g_aoh);  cudaGetSymbolAddress((void**)&aol, g_aol);
    cudaGetSymbolAddress((void**)&qwh, g_qwh);  cudaGetSymbolAddress((void**)&qwl, g_qwl);
    cudaGetSymbolAddress((void**)&kvwh, g_kvwh); cudaGetSymbolAddress((void**)&kvwl, g_kvwl);
    cudaGetSymbolAddress((void**)&srh, g_srh);  cudaGetSymbolAddress((void**)&srl, g_srl);
    cudaGetSymbolAddress((void**)&prh, g_prh);  cudaGetSymbolAddress((void**)&prl, g_prl);

    cudaFuncSetAttribute(hgemm<0>, cudaFuncAttributeMaxDynamicSharedMemorySize, HG_SMEM);
    cudaFuncSetAttribute(hgemm_qc, cudaFuncAttributeMaxDynamicSharedMemorySize, HG_SMEM);
    cudaFuncSetAttribute(attn_mma, cudaFuncAttributeMaxDynamicSharedMemorySize, AT_SMEM);

    f2hl<<<(B_*N_*C_) / 1024, 256>>>(x, xh, xl, B_*N_*C_);
    f2hl<<<(C_*C_) / 1024, 256>>>(q_w, qwh, qwl, C_*C_);
    f2hl<<<(2*C_*C_) / 1024, 256>>>(kv_w, kvwh, kvwl, 2*C_*C_);
    f2hl<<<(C_*C_) / 1024, 256>>>(proj_w, prh, prl, C_*C_);
    srhl<<<(C_*KCONV) / 256, 256>>>(sr_w, srh, srl);

    hgemm_qc<<<dim3(4, 160), 256, HG_SMEM>>>(xh, xl, srh, srl, sr_b, xrh, xrl,
                                             qwh, qwl, qh, ql);
    hgemm<0><<<dim3(8, 32), 256, HG_SMEM>>>(xrh, xrl, kvwh, kvwl, nullptr,
                                            nullptr, kvh, kvl, 2*C_, C_);
    attn_mma<<<dim3(N_ / 128, 8, B_), 256, AT_SMEM>>>(qh, ql, kvh, kvl, aoh, aol);
    hgemm<0><<<dim3(4, 128), 256, HG_SMEM>>>(aoh, aol, prh, prl, proj_b,
                                             out, nullptr, nullptr, C_, C_);
}

// round 17
// speedup vs baseline: 2.7323x; 1.0128x over previous
#include <cuda_runtime.h>
#include <cuda_bf16.h>
#include <cstdint>

#define B_   4
#define N_   4096
#define C_   512
#define NK_  1024
#define KCONV 2048
typedef __nv_bfloat16 bf16;

// ---------------- scratch ----------------
__device__ bf16 g_xh [B_*N_*C_],  g_xl [B_*N_*C_];
__device__ bf16 g_qh [B_*N_*C_],  g_ql [B_*N_*C_];
__device__ bf16 g_xrh[B_*NK_*C_], g_xrl[B_*NK_*C_];
__device__ bf16 g_kvh[B_*NK_*2*C_], g_kvl[B_*NK_*2*C_];
__device__ bf16 g_aoh[B_*N_*C_],  g_aol[B_*N_*C_];
__device__ bf16 g_qwh [C_*C_],    g_qwl [C_*C_];
__device__ bf16 g_kvwh[2*C_*C_],  g_kvwl[2*C_*C_];
__device__ bf16 g_srh [C_*KCONV], g_srl [C_*KCONV];
__device__ bf16 g_prh [C_*C_],    g_prl [C_*C_];

// ---------------- helpers ----------------
__device__ __forceinline__ uint32_t s2u(const void* p){
    uint32_t a;
    asm("{ .reg .u64 t; cvta.to.shared.u64 t, %1; cvt.u32.u64 %0, t; }" : "=r"(a) : "l"(p));
    return a;
}
__device__ __forceinline__ void mma16816(float* c, const uint32_t* a, const uint32_t* b){
    asm volatile("mma.sync.aligned.m16n8k16.row.col.f32.bf16.bf16.f32 "
        "{%0,%1,%2,%3}, {%4,%5,%6,%7}, {%8,%9}, {%0,%1,%2,%3};"
        : "+f"(c[0]), "+f"(c[1]), "+f"(c[2]), "+f"(c[3])
        : "r"(a[0]), "r"(a[1]), "r"(a[2]), "r"(a[3]), "r"(b[0]), "r"(b[1]));
}
__device__ __forceinline__ void split2(float x, float y, uint32_t& h, uint32_t& l){
    __nv_bfloat162 hh = __float22bfloat162_rn(make_float2(x, y));
    float2 hf = __bfloat1622float2(hh);
    __nv_bfloat162 ll = __float22bfloat162_rn(make_float2(x - hf.x, y - hf.y));
    h = *(uint32_t*)&hh; l = *(uint32_t*)&ll;
}
__device__ __forceinline__ void ldmx4(uint32_t* r, uint32_t a){
    asm volatile("ldmatrix.sync.aligned.m8n8.x4.shared.b16 {%0,%1,%2,%3}, [%4];"
        : "=r"(r[0]), "=r"(r[1]), "=r"(r[2]), "=r"(r[3]) : "r"(a));
}
__device__ __forceinline__ void ldmx4t(uint32_t* r, uint32_t a){
    asm volatile("ldmatrix.sync.aligned.m8n8.x4.trans.shared.b16 {%0,%1,%2,%3}, [%4];"
        : "=r"(r[0]), "=r"(r[1]), "=r"(r[2]), "=r"(r[3]) : "r"(a));
}
__device__ __forceinline__ void cpa(uint32_t s, const void* g){
    asm volatile("cp.async.cg.shared.global [%0], [%1], 16;" :: "r"(s), "l"(g));
}
#define CP_COMMIT() asm volatile("cp.async.commit_group;" ::: "memory")

// ---------------- prep: fp32 -> bf16 hi/lo ----------------
__global__ void f2hl(const float* __restrict__ s, bf16* __restrict__ h,
                     bf16* __restrict__ l, int n){
    int i = (blockIdx.x * 256 + threadIdx.x) * 4;
    if (i >= n) return;
    float4 v = *reinterpret_cast<const float4*>(s + i);
    uint32_t h0, l0, h1, l1;
    split2(v.x, v.y, h0, l0);
    split2(v.z, v.w, h1, l1);
    *reinterpret_cast<uint2*>(h + i) = make_uint2(h0, h1);
    *reinterpret_cast<uint2*>(l + i) = make_uint2(l0, l1);
}
__global__ void srhl(const float* __restrict__ w, bf16* __restrict__ h,
                     bf16* __restrict__ l){
    int idx = blockIdx.x * 256 + threadIdx.x;    // over 512*2048
    int n = idx >> 11, k = idx & 2047;
    int ij = k >> 9, ci = k & 511;
    float v = w[((size_t)n * C_ + ci) * 4 + ij];
    bf16 hh = __float2bfloat16(v);
    h[idx] = hh;
    l[idx] = __float2bfloat16(v - __bfloat162float(hh));
}

// ---------------- hgemm device body (unchanged, known-good) ----------------
#define HG_STG   40960
#define HG_SMEM  (2 * HG_STG)

template <int MODE>
__device__ __forceinline__
void hgemm_dev(char* smc,
               const bf16* __restrict__ Ah_, const bf16* __restrict__ Al_,
               const bf16* __restrict__ Bh_, const bf16* __restrict__ Bl_,
               const float* __restrict__ bias, float* __restrict__ outF,
               bf16* __restrict__ outH, bf16* __restrict__ outL,
               int N, int K, int bx, int by) {
    const uint32_t sb = s2u(smc);
    const int tid  = threadIdx.x;
    const int lane = tid & 31, warp = tid >> 5;
    const int wm = (warp >> 2) * 64, wn = (warp & 3) * 32;

    float acc[4][4][4];
#pragma unroll
    for (int i = 0; i < 4; i++)
#pragma unroll
        for (int j = 0; j < 4; j++)
#pragma unroll
            for (int r = 0; r < 4; r++) acc[i][j][r] = 0.f;

    const int NC = K >> 5;

    auto stage_load = [&](int kci, int st){
        int k0 = kci << 5;
#pragma unroll
        for (int p = 0; p < 2; p++) {
            int id = tid + p * 256;
            int row = id >> 2, ch = id & 3;
            int kg = k0 + ch * 8;
            size_t aoff;
            if (MODE == 0) {
                aoff = (size_t)(by + row) * K + kg;
            } else {
                int m = by + row;
                int bb = m >> 10, pp = m & 1023, ph = pp >> 5, pw = pp & 31;
                int ij = kg >> 9, ci = kg & 511;
                int pix = (2 * ph + (ij >> 1)) * 64 + 2 * pw + (ij & 1);
                aoff = ((size_t)(bb << 12) + pix) * C_ + ci;
            }
            size_t boff = (size_t)(bx + row) * K + kg;
            uint32_t si = sb + st * HG_STG + row * 80 + ch * 16;
            cpa(si,         Ah_ + aoff);
            cpa(si + 10240, Al_ + aoff);
            cpa(si + 20480, Bh_ + boff);
            cpa(si + 30720, Bl_ + boff);
        }
        CP_COMMIT();
    };

    const int lm = lane >> 3, lr = lane & 7;
    const int aro = (lm & 1) * 8, aco = (lm >> 1) * 4;
    const int bro = (lm >> 1) * 8, bco = (lm & 1) * 4;

    stage_load(0, 0);

    for (int i = 0; i < NC; i++) {
        int st = i & 1;
        if (i + 1 < NC) stage_load(i + 1, st ^ 1);
        if (i + 1 < NC) asm volatile("cp.async.wait_group 1;" ::: "memory");
        else            asm volatile("cp.async.wait_group 0;" ::: "memory");
        __syncthreads();

        const uint32_t sA = sb + st * HG_STG;
#pragma unroll
        for (int kh = 0; kh < 2; kh++) {
            uint32_t ah[4][4], al[4][4], bh[2][4], bl[2][4];
#pragma unroll
            for (int mt = 0; mt < 4; mt++) {
                uint32_t ad = sA + ((wm + 16 * mt + aro + lr) * 20 + kh * 8 + aco) * 4;
                ldmx4(ah[mt], ad);
                ldmx4(al[mt], ad + 10240);
            }
#pragma unroll
            for (int ntp = 0; ntp < 2; ntp++) {
                uint32_t bd = sA + 20480 + ((wn + 16 * ntp + bro + lr) * 20 + kh * 8 + bco) * 4;
                ldmx4(bh[ntp], bd);
                ldmx4(bl[ntp], bd + 10240);
            }
#pragma unroll
            for (int mt = 0; mt < 4; mt++)
#pragma unroll
                for (int nt = 0; nt < 4; nt++)
                    mma16816(acc[mt][nt], ah[mt], &bh[nt >> 1][(nt & 1) * 2]);
#pragma unroll
            for (int mt = 0; mt < 4; mt++)
#pragma unroll
                for (int nt = 0; nt < 4; nt++)
                    mma16816(acc[mt][nt], ah[mt], &bl[nt >> 1][(nt & 1) * 2]);
#pragma unroll
            for (int mt = 0; mt < 4; mt++)
#pragma unroll
                for (int nt = 0; nt < 4; nt++)
                    mma16816(acc[mt][nt], al[mt], &bh[nt >> 1][(nt & 1) * 2]);
        }
        __syncthreads();
    }

    const int rq = lane >> 2, cq = 2 * (lane & 3);
#pragma unroll
    for (int mt = 0; mt < 4; mt++) {
#pragma unroll
        for (int nt = 0; nt < 4; nt++) {
            int col = bx + wn + 8 * nt + cq;
            float b0 = bias ? bias[col] : 0.f;
            float b1 = bias ? bias[col + 1] : 0.f;
            int r0 = by + wm + 16 * mt + rq;
            float v00 = acc[mt][nt][0] + b0, v01 = acc[mt][nt][1] + b1;
            float v10 = acc[mt][nt][2] + b0, v11 = acc[mt][nt][3] + b1;
            if (outF) {
                *reinterpret_cast<float2*>(outF + (size_t)r0 * N + col) = make_float2(v00, v01);
                *reinterpret_cast<float2*>(outF + (size_t)(r0 + 8) * N + col) = make_float2(v10, v11);
            }
            if (outH) {
                uint32_t h, l;
                split2(v00, v01, h, l);
                *reinterpret_cast<uint32_t*>(outH + (size_t)r0 * N + col) = h;
                *reinterpret_cast<uint32_t*>(outL + (size_t)r0 * N + col) = l;
                split2(v10, v11, h, l);
                *reinterpret_cast<uint32_t*>(outH + (size_t)(r0 + 8) * N + col) = h;
                *reinterpret_cast<uint32_t*>(outL + (size_t)(r0 + 8) * N + col) = l;
            }
        }
    }
}

template <int MODE>
__global__ __launch_bounds__(256)
void hgemm(const bf16* __restrict__ Ah_, const bf16* __restrict__ Al_,
           const bf16* __restrict__ Bh_, const bf16* __restrict__ Bl_,
           const float* __restrict__ bias, float* __restrict__ outF,
           bf16* __restrict__ outH, bf16* __restrict__ outL, int N, int K) {
    extern __shared__ char smc[];
    hgemm_dev<MODE>(smc, Ah_, Al_, Bh_, Bl_, bias, outF, outH, outL,
                    N, K, blockIdx.x * 128, blockIdx.y * 128);
}

__global__ __launch_bounds__(256)
void hgemm_qc(const bf16* __restrict__ xh, const bf16* __restrict__ xl,
              const bf16* __restrict__ srh, const bf16* __restrict__ srl,
              const float* __restrict__ sr_b,
              bf16* __restrict__ xrh, bf16* __restrict__ xrl,
              const bf16* __restrict__ qwh, const bf16* __restrict__ qwl,
              bf16* __restrict__ qh, bf16* __restrict__ ql) {
    extern __shared__ char smc[];
    if (blockIdx.y < 32)
        hgemm_dev<1>(smc, xh, xl, srh, srl, sr_b, nullptr, xrh, xrl,
                     C_, KCONV, blockIdx.x * 128, blockIdx.y * 128);
    else
        hgemm_dev<0>(smc, xh, xl, qwh, qwl, nullptr, nullptr, qh, ql,
                     C_, C_, blockIdx.x * 128, (blockIdx.y - 32) * 128);
}

// ---------------- pipelined flash attention, 256 queries/block ----------------
// grid (16, 8, 4); 8 warps x 32 q (2 m-tiles). KV tiles of 64 keys, 2-stage cp.async.
// SMEM bytes: Qh[0,36864) Ql[36864,73728) KVstage0[73728,110592) KVstage1[110592,147456)
// KV stage layout (u32): Kh[64*36] Kl Vh Vl (2304 u32 each).
#define AT_SMEM 147456

__global__ __launch_bounds__(256)
void attn_mma(const bf16* __restrict__ Qh_, const bf16* __restrict__ Ql_,
              const bf16* __restrict__ KVh_, const bf16* __restrict__ KVl_,
              bf16* __restrict__ Oh, bf16* __restrict__ Ol) {
    extern __shared__ uint32_t su[];
    const uint32_t sb = s2u(su);

    const int tid  = threadIdx.x;
    const int lane = tid & 31, warp = tid >> 5;
    const int rq = lane >> 2, tq = lane & 3;
    const int qb = blockIdx.x * 256;
    const int h  = blockIdx.y;
    const int b  = blockIdx.z;

    const int lm = lane >> 3, lr = lane & 7;
    const int aro = (lm & 1) * 8, aco = (lm >> 1) * 4;
    const int bro = (lm >> 1) * 8, bco = (lm & 1) * 4;
    const int vro = (lm & 1) * 8, vns = (lm >> 1);

    // ---- load Q tile [256 q][64 d] h/l: 4096 16B-chunks ----
    {
        size_t qo = ((size_t)(b * N_ + qb)) * C_ + h * 64;
#pragma unroll
        for (int p = 0; p < 16; p++) {
            int id = tid + p * 256;                 // 0..4095
            int arr = id >> 11, rem = id & 2047;    // 2048 chunks per array
            int row = rem >> 3, ch = rem & 7;
            const bf16* src = (arr ? Ql_ : Qh_) + qo + (size_t)row * C_ + ch * 8;
            uint32_t* dst = su + arr * 9216 + row * 36 + ch * 4;
            *reinterpret_cast<uint4*>(dst) = *reinterpret_cast<const uint4*>(src);
        }
    }
    __syncthreads();

    // ---- Q-hi fragments resident; Q-lo stays in smem ----
    uint32_t qah[2][4][4];
#pragma unroll
    for (int mt = 0; mt < 2; mt++)
#pragma unroll
        for (int kc = 0; kc < 4; kc++)
            ldmx4(qah[mt][kc],
                  sb + ((warp * 32 + mt * 16 + aro + lr) * 36 + kc * 8 + aco) * 4);

    float oacc[2][8][4];
#pragma unroll
    for (int mt = 0; mt < 2; mt++)
#pragma unroll
        for (int nt = 0; nt < 8; nt++)
#pragma unroll
            for (int r = 0; r < 4; r++) oacc[mt][nt][r] = 0.f;
    float m_[2][2], l_[2][2];
#pragma unroll
    for (int mt = 0; mt < 2; mt++) { m_[mt][0] = m_[mt][1] = -1e30f; l_[mt][0] = l_[mt][1] = 0.f; }

    const size_t kvo = (size_t)b * NK_ * (2 * C_) + h * 64;

    auto kv_load = [&](int t, uint32_t dstb){
#pragma unroll
        for (int p = 0; p < 8; p++) {
            int id = tid + p * 256;                 // 0..2047
            int arr = id >> 9, rem = id & 511;
            int row = rem >> 3, ch = rem & 7;
            const bf16* base = (arr & 1) ? KVl_ : KVh_;
            size_t off = kvo + (size_t)(t * 64 + row) * (2 * C_) + ((arr >> 1) ? C_ : 0) + ch * 8;
            cpa(dstb + (arr * 2304 + row * 36 + ch * 4) * 4, base + off);
        }
        CP_COMMIT();
    };

    kv_load(0, sb + 73728);                         // tile 0 -> stage0

    for (int t = 0; t < NK_ / 64; t++) {
        const uint32_t cb = (t & 1) ? sb + 110592 : sb + 73728;
        asm volatile("cp.async.wait_group 0;" ::: "memory");
        __syncthreads();
        if (t + 1 < NK_ / 64)
            kv_load(t + 1, (t & 1) ? sb + 73728 : sb + 110592);

        // ---- S = Q K^T (K-frags shared across both m-tiles) ----
        float sacc[2][8][4];
#pragma unroll
        for (int mt = 0; mt < 2; mt++)
#pragma unroll
            for (int nt = 0; nt < 8; nt++)
#pragma unroll
                for (int r = 0; r < 4; r++) sacc[mt][nt][r] = 0.f;
#pragma unroll
        for (int kc = 0; kc < 4; kc++) {
            uint32_t qalf[2][4];
#pragma unroll
            for (int mt = 0; mt < 2; mt++)
                ldmx4(qalf[mt],
                      sb + 36864 + ((warp * 32 + mt * 16 + aro + lr) * 36 + kc * 8 + aco) * 4);
#pragma unroll
            for (int ng = 0; ng < 2; ng++) {
                uint32_t bh4[2][4], bl4[2][4];
#pragma unroll
                for (int j = 0; j < 2; j++) {
                    uint32_t bd = cb + ((16 * (2 * ng + j) + bro + lr) * 36 + kc * 8 + bco) * 4;
                    ldmx4(bh4[j], bd);
                    ldmx4(bl4[j], bd + 9216);
                }
#pragma unroll
                for (int mt = 0; mt < 2; mt++)
#pragma unroll
                    for (int j = 0; j < 2; j++)
#pragma unroll
                        for (int s = 0; s < 2; s++) {
                            float* d = sacc[mt][2 * (2 * ng + j) + s];
                            mma16816(d, qah[mt][kc], &bh4[j][s * 2]);
                            mma16816(d, qah[mt][kc], &bl4[j][s * 2]);
                            mma16816(d, qalf[mt],    &bh4[j][s * 2]);
                        }
            }
        }

        // ---- online softmax (per m-tile) ----
        uint32_t pah[2][4][4], pal[2][4][4];
#pragma unroll
        for (int mt = 0; mt < 2; mt++) {
            float tm0 = -1e30f, tm1 = -1e30f;
#pragma unroll
            for (int nt = 0; nt < 8; nt++) {
                tm0 = fmaxf(tm0, fmaxf(sacc[mt][nt][0], sacc[mt][nt][1]));
                tm1 = fmaxf(tm1, fmaxf(sacc[mt][nt][2], sacc[mt][nt][3]));
            }
#pragma unroll
            for (int o = 1; o <= 2; o <<= 1) {
                tm0 = fmaxf(tm0, __shfl_xor_sync(0xffffffffu, tm0, o));
                tm1 = fmaxf(tm1, __shfl_xor_sync(0xffffffffu, tm1, o));
            }
            float mn0 = fmaxf(m_[mt][0], tm0), mn1 = fmaxf(m_[mt][1], tm1);
            float al0 = __expf(0.125f * (m_[mt][0] - mn0));
            float al1 = __expf(0.125f * (m_[mt][1] - mn1));
            float rs0 = 0.f, rs1 = 0.f;
#pragma unroll
            for (int nt = 0; nt < 8; nt++) {
                float p0 = __expf(0.125f * (sacc[mt][nt][0] - mn0));
                float p1 = __expf(0.125f * (sacc[mt][nt][1] - mn0));
                float p2 = __expf(0.125f * (sacc[mt][nt][2] - mn1));
                float p3 = __expf(0.125f * (sacc[mt][nt][3] - mn1));
                sacc[mt][nt][0] = p0; sacc[mt][nt][1] = p1;
                sacc[mt][nt][2] = p2; sacc[mt][nt][3] = p3;
                rs0 += p0 + p1; rs1 += p2 + p3;
            }
#pragma unroll
            for (int o = 1; o <= 2; o <<= 1) {
                rs0 += __shfl_xor_sync(0xffffffffu, rs0, o);
                rs1 += __shfl_xor_sync(0xffffffffu, rs1, o);
            }
            l_[mt][0] = l_[mt][0] * al0 + rs0;  l_[mt][1] = l_[mt][1] * al1 + rs1;
            m_[mt][0] = mn0;                    m_[mt][1] = mn1;
#pragma unroll
            for (int nt = 0; nt < 8; nt++) {
                oacc[mt][nt][0] *= al0; oacc[mt][nt][1] *= al0;
                oacc[mt][nt][2] *= al1; oacc[mt][nt][3] *= al1;
            }
            // P (C-frag) -> A-frags, registers only
#pragma unroll
            for (int kc = 0; kc < 4; kc++) {
                split2(sacc[mt][2*kc][0],   sacc[mt][2*kc][1],   pah[mt][kc][0], pal[mt][kc][0]);
                split2(sacc[mt][2*kc][2],   sacc[mt][2*kc][3],   pah[mt][kc][1], pal[mt][kc][1]);
                split2(sacc[mt][2*kc+1][0], sacc[mt][2*kc+1][1], pah[mt][kc][2], pal[mt][kc][2]);
                split2(sacc[mt][2*kc+1][2], sacc[mt][2*kc+1][3], pah[mt][kc][3], pal[mt][kc][3]);
            }
        }

        // ---- O += P V (V-frags shared across both m-tiles) ----
#pragma unroll
        for (int kc = 0; kc < 4; kc++) {
#pragma unroll
            for (int ng = 0; ng < 2; ng++) {
                uint32_t vh4[2][4], vl4[2][4];
#pragma unroll
                for (int j = 0; j < 2; j++) {
                    uint32_t vd = cb + 18432 +
                        ((16 * kc + vro + lr) * 36 + (2 * (2 * ng + j) + vns) * 4) * 4;
                    ldmx4t(vh4[j], vd);
                    ldmx4t(vl4[j], vd + 9216);
                }
#pragma unroll
                for (int mt = 0; mt < 2; mt++)
#pragma unroll
                    for (int j = 0; j < 2; j++)
#pragma unroll
                        for (int s = 0; s < 2; s++) {
                            float* d = oacc[mt][2 * (2 * ng + j) + s];
                            mma16816(d, pah[mt][kc], &vh4[j][s * 2]);
                            mma16816(d, pal[mt][kc], &vh4[j][s * 2]);
                            mma16816(d, pah[mt][kc], &vl4[j][s * 2]);
                        }
            }
        }
    }

    // ---- epilogue -> bf16 h/l ----
    size_t ob = (size_t)(b * N_) * C_ + h * 64;
#pragma unroll
    for (int mt = 0; mt < 2; mt++) {
        float inv0 = 1.f / l_[mt][0], inv1 = 1.f / l_[mt][1];
        int row0 = qb + warp * 32 + mt * 16 + rq;
#pragma unroll
        for (int nt = 0; nt < 8; nt++) {
            int d = 8 * nt + 2 * tq;
            uint32_t hh, ll;
            split2(oacc[mt][nt][0] * inv0, oacc[mt][nt][1] * inv0, hh, ll);
            *reinterpret_cast<uint32_t*>(Oh + ob + (size_t)row0 * C_ + d) = hh;
            *reinterpret_cast<uint32_t*>(Ol + ob + (size_t)row0 * C_ + d) = ll;
            split2(oacc[mt][nt][2] * inv1, oacc[mt][nt][3] * inv1, hh, ll);
            *reinterpret_cast<uint32_t*>(Oh + ob + (size_t)(row0 + 8) * C_ + d) = hh;
            *reinterpret_cast<uint32_t*>(Ol + ob + (size_t)(row0 + 8) * C_ + d) = ll;
        }
    }
}

// ---------------- launch ----------------
extern "C" void kernel_launch(void* const* d_in, const int* in_sizes, int n_in,
                              void* d_out, int out_size) {
    const float* x      = (const float*)d_in[0];
    const float* q_w    = (const float*)d_in[1];
    const float* kv_w   = (const float*)d_in[2];
    const float* sr_w   = (const float*)d_in[3];
    const float* sr_b   = (const float*)d_in[4];
    const float* proj_w = (const float*)d_in[5];
    const float* proj_b = (const float*)d_in[6];
    float* out = (float*)d_out;

    bf16 *xh, *xl, *qh, *ql, *xrh, *xrl, *kvh, *kvl, *aoh, *aol;
    bf16 *qwh, *qwl, *kvwh, *kvwl, *srh, *srl, *prh, *prl;
    cudaGetSymbolAddress((void**)&xh,  g_xh);   cudaGetSymbolAddress((void**)&xl,  g_xl);
    cudaGetSymbolAddress((void**)&qh,  g_qh);   cudaGetSymbolAddress((void**)&ql,  g_ql);
    cudaGetSymbolAddress((void**)&xrh, g_xrh);  cudaGetSymbolAddress((void**)&xrl, g_xrl);
    cudaGetSymbolAddress((void**)&kvh, g_kvh);  cudaGetSymbolAddress((void**)&kvl, g_kvl);
    cudaGetSymbolAddress((void**)&aoh, g_aoh);  cudaGetSymbolAddress((void**)&aol, g_aol);
    cudaGetSymbolAddress((void**)&qwh, g_qwh);  cudaGetSymbolAddress((void**)&qwl, g_qwl);
    cudaGetSymbolAddress((void**)&kvwh, g_kvwh); cudaGetSymbolAddress((void**)&kvwl, g_kvwl);
    cudaGetSymbolAddress((void**)&srh, g_srh);  cudaGetSymbolAddress((void**)&srl, g_srl);
    cudaGetSymbolAddress((void**)&prh, g_prh);  cudaGetSymbolAddress((void**)&prl, g_prl);

    cudaFuncSetAttribute(hgemm<0>, cudaFuncAttributeMaxDynamicSharedMemorySize, HG_SMEM);
    cudaFuncSetAttribute(hgemm_qc, cudaFuncAttributeMaxDynamicSharedMemorySize, HG_SMEM);
    cudaFuncSetAttribute(attn_mma, cudaFuncAttributeMaxDynamicSharedMemorySize, AT_SMEM);

    f2hl<<<(B_*N_*C_) / 1024, 256>>>(x, xh, xl, B_*N_*C_);
    f2hl<<<(C_*C_) / 1024, 256>>>(q_w, qwh, qwl, C_*C_);
    f2hl<<<(2*C_*C_) / 1024, 256>>>(kv_w, kvwh, kvwl, 2*C_*C_);
    f2hl<<<(C_*C_) / 1024, 256>>>(proj_w, prh, prl, C_*C_);
    srhl<<<(C_*KCONV) / 256, 256>>>(sr_w, srh, srl);

    hgemm_qc<<<dim3(4, 160), 256, HG_SMEM>>>(xh, xl, srh, srl, sr_b, xrh, xrl,
                                             qwh, qwl, qh, ql);
    hgemm<0><<<dim3(8, 32), 256, HG_SMEM>>>(xrh, xrl, kvwh, kvwl, nullptr,
                                            nullptr, kvh, kvl, 2*C_, C_);
    attn_mma<<<dim3(N_ / 256, 8, B_), 256, AT_SMEM>>>(qh, ql, kvh, kvl, aoh, aol);
    hgemm<0><<<dim3(4, 128), 256, HG_SMEM>>>(aoh, aol, prh, prl, proj_b,
                                             out, nullptr, nullptr, C_, C_);
}